// round 9
// baseline (speedup 1.0000x reference)
#include <cuda_runtime.h>
#include <cuda_bf16.h>
#include <math.h>
#include <cstdint>

#define D     256
#define D4    64
#define D16   32                     // uint4 per 256-bf16 row
#define MAX_NSAMP  50000
#define MAX_NSRC   50000
#define MAX_NTOTAL 200000
#define MAX_E      1600000
#define SCAN_TPB   256
#define SCAN_EPB   2048
#define DECAY_PERSIST 254            // wave-1 leftover slots next to 782 GEMM blocks

// ---------------- scratch (static device globals; no allocation) -------------
// Self-cleaning invariants (valid at entry of every kernel_launch call):
//   g_hist == 0 (zeroed by k_scatter), g_cursor == 0 (zeroed by k_scan),
//   g_winner == 0 (zeroed by decay blocks of k_gemm_decay; winner = idx+1, 0 = empty)
__device__ __nv_bfloat16 g_xbf[MAX_NSRC * D];
__device__ __nv_bfloat16 g_feat_hi[MAX_NSAMP * D];
__device__ __nv_bfloat16 g_feat_lo[MAX_NSAMP * D];
__device__ __nv_bfloat16 g_wt_hi[D * D];             // W^T hi  [n][k]
__device__ __nv_bfloat16 g_wt_lo[D * D];             // W^T lo
__device__ int   g_hist[MAX_NSAMP];
__device__ int   g_cursor[MAX_NSAMP];
__device__ int   g_rowStart[MAX_NSAMP + 1];
__device__ int   g_winner[MAX_NTOTAL];
__device__ int2  g_edge[MAX_E];

// ================= prep: x->bf16, W^T split, hist, winner ====================
__global__ void k_prep(const float* __restrict__ x, const float* __restrict__ W,
                       const int* __restrict__ row, int E,
                       const int* __restrict__ nodes, int nsamp,
                       int nsrc, int convB, int wB) {
    int b = blockIdx.x;
    int t = threadIdx.x;
    if (b < convB) {
        long long total = (long long)nsrc * D4;
        long long i0 = (long long)b * 1024 + t;
        const float4* x4 = (const float4*)x;
#pragma unroll
        for (int j = 0; j < 4; j++) {
            long long i = i0 + j * 256;
            if (i < total) {
                float4 v = x4[i];
                __nv_bfloat162 p0 = __floats2bfloat162_rn(v.x, v.y);
                __nv_bfloat162 p1 = __floats2bfloat162_rn(v.z, v.w);
                uint2 u;
                u.x = *(uint32_t*)&p0;
                u.y = *(uint32_t*)&p1;
                ((uint2*)g_xbf)[i] = u;
            }
        }
        return;
    }
    if (b < convB + wB) {
        int i = (b - convB) * 256 + t;
        if (i < D * D) {
            int k = i >> 8, n = i & 255;
            float w = W[k * D + n];
            __nv_bfloat16 hi = __float2bfloat16_rn(w);
            __nv_bfloat16 lo = __float2bfloat16_rn(w - __bfloat162float(hi));
            g_wt_hi[n * D + k] = hi;
            g_wt_lo[n * D + k] = lo;
        }
        return;
    }
    int i = (b - convB - wB) * 256 + t;
    if (i < E) atomicAdd(&g_hist[row[i]], 1);
    if (i < nsamp) atomicMax(&g_winner[nodes[i]], i + 1);   // 0 = empty
}

// ===== single-kernel scan: each block sums its own prefix (G~25, cheap) ======
__global__ __launch_bounds__(SCAN_TPB) void k_scan(int n, int E) {
    __shared__ int sred[SCAN_TPB / 32];
    __shared__ int ws[SCAN_TPB / 32];
    int t = threadIdx.x, lane = t & 31, w = t >> 5;
    int tileStart = blockIdx.x * SCAN_EPB;

    int ps = 0;
    for (int i = t; i < tileStart; i += SCAN_TPB) ps += g_hist[i];
#pragma unroll
    for (int o = 16; o > 0; o >>= 1) ps += __shfl_xor_sync(0xffffffff, ps, o);
    if (lane == 0) sred[w] = ps;

    int base = tileStart + t * 8;
    int v[8], sum = 0;
#pragma unroll
    for (int j = 0; j < 8; j++) {
        int idx = base + j;
        v[j] = (idx < n) ? g_hist[idx] : 0;
        if (idx < n) g_cursor[idx] = 0;
        sum += v[j];
    }
    int x = sum;
#pragma unroll
    for (int o = 1; o < 32; o <<= 1) {
        int y = __shfl_up_sync(0xffffffff, x, o);
        if (lane >= o) x += y;
    }
    if (lane == 31) ws[w] = x;
    __syncthreads();
    if (t == 0) {
        int total = 0;
#pragma unroll
        for (int i = 0; i < SCAN_TPB / 32; i++) total += sred[i];
        int r = total;
#pragma unroll
        for (int i = 0; i < SCAN_TPB / 32; i++) { int q = ws[i]; ws[i] = r; r += q; }
    }
    __syncthreads();
    int run = ws[w] + (x - sum);
#pragma unroll
    for (int j = 0; j < 8; j++) {
        int idx = base + j;
        if (idx < n) g_rowStart[idx] = run;
        run += v[j];
    }
    if (blockIdx.x == 0 && t == 0) g_rowStart[n] = E;
}

// ============ scatter edges into row-sorted order (+ zero hist) ==============
__global__ void k_scatter(const int* __restrict__ row, const int* __restrict__ col,
                          const float* __restrict__ val, int E, int nsamp) {
    int i = blockIdx.x * blockDim.x + threadIdx.x;
    if (i < nsamp) g_hist[i] = 0;               // clean for next call
    if (i < E) {
        int r = row[i];
        int p = g_rowStart[r] + atomicAdd(&g_cursor[r], 1);
        int2 e;
        e.x = col[i];
        e.y = __float_as_int(val[i]);
        g_edge[p] = e;
    }
}

// ========= SpMM only (warp-per-row, 16B gathers, 8-edge unroll) ==============
__global__ __launch_bounds__(256) void k_spmm(
    const int* __restrict__ nodes,
    const float4* __restrict__ y4, float4* __restrict__ newY4, int nsamp) {
    int t = threadIdx.x;
    int warp = t >> 5, lane = t & 31;
    int r = blockIdx.x * 8 + warp;
    if (r >= nsamp) return;
    int e = g_rowStart[r];
    int end = g_rowStart[r + 1];
    const uint4* xb = (const uint4*)g_xbf;
    float acc[8];
#pragma unroll
    for (int q = 0; q < 8; q++) acc[q] = 0.f;

#pragma unroll 1
    for (; e + 8 <= end; e += 8) {
        uint4 u[8];
        float vv[8];
#pragma unroll
        for (int j = 0; j < 8; j++) {
            int2 ed = g_edge[e + j];
            vv[j] = __int_as_float(ed.y);
            u[j] = xb[(size_t)ed.x * D16 + lane];
        }
#pragma unroll
        for (int j = 0; j < 8; j++) {
            float2 p0 = __bfloat1622float2(*(__nv_bfloat162*)&u[j].x);
            float2 p1 = __bfloat1622float2(*(__nv_bfloat162*)&u[j].y);
            float2 p2 = __bfloat1622float2(*(__nv_bfloat162*)&u[j].z);
            float2 p3 = __bfloat1622float2(*(__nv_bfloat162*)&u[j].w);
            float v = vv[j];
            acc[0] = fmaf(v, p0.x, acc[0]); acc[1] = fmaf(v, p0.y, acc[1]);
            acc[2] = fmaf(v, p1.x, acc[2]); acc[3] = fmaf(v, p1.y, acc[3]);
            acc[4] = fmaf(v, p2.x, acc[4]); acc[5] = fmaf(v, p2.y, acc[5]);
            acc[6] = fmaf(v, p3.x, acc[6]); acc[7] = fmaf(v, p3.y, acc[7]);
        }
    }
    for (; e < end; e++) {
        int2 ed = g_edge[e];
        float v = __int_as_float(ed.y);
        uint4 u = xb[(size_t)ed.x * D16 + lane];
        float2 p0 = __bfloat1622float2(*(__nv_bfloat162*)&u.x);
        float2 p1 = __bfloat1622float2(*(__nv_bfloat162*)&u.y);
        float2 p2 = __bfloat1622float2(*(__nv_bfloat162*)&u.z);
        float2 p3 = __bfloat1622float2(*(__nv_bfloat162*)&u.w);
        acc[0] = fmaf(v, p0.x, acc[0]); acc[1] = fmaf(v, p0.y, acc[1]);
        acc[2] = fmaf(v, p1.x, acc[2]); acc[3] = fmaf(v, p1.y, acc[3]);
        acc[4] = fmaf(v, p2.x, acc[4]); acc[5] = fmaf(v, p2.y, acc[5]);
        acc[6] = fmaf(v, p3.x, acc[6]); acc[7] = fmaf(v, p3.y, acc[7]);
    }

    int node = nodes[r];
    float4 y0 = y4[(size_t)node * D4 + lane * 2];
    float4 y1 = y4[(size_t)node * D4 + lane * 2 + 1];
    float g[8];
    g[0] = fmaf(0.1f, acc[0], 0.9f * y0.x);
    g[1] = fmaf(0.1f, acc[1], 0.9f * y0.y);
    g[2] = fmaf(0.1f, acc[2], 0.9f * y0.z);
    g[3] = fmaf(0.1f, acc[3], 0.9f * y0.w);
    g[4] = fmaf(0.1f, acc[4], 0.9f * y1.x);
    g[5] = fmaf(0.1f, acc[5], 0.9f * y1.y);
    g[6] = fmaf(0.1f, acc[6], 0.9f * y1.z);
    g[7] = fmaf(0.1f, acc[7], 0.9f * y1.w);

    uint4 uh, ul;
    {
        __nv_bfloat16 h[8], l[8];
#pragma unroll
        for (int q = 0; q < 8; q++) {
            h[q] = __float2bfloat16_rn(g[q]);
            l[q] = __float2bfloat16_rn(g[q] - __bfloat162float(h[q]));
        }
        __nv_bfloat162 a0 = __halves2bfloat162(h[0], h[1]);
        __nv_bfloat162 a1 = __halves2bfloat162(h[2], h[3]);
        __nv_bfloat162 a2 = __halves2bfloat162(h[4], h[5]);
        __nv_bfloat162 a3 = __halves2bfloat162(h[6], h[7]);
        uh.x = *(uint32_t*)&a0; uh.y = *(uint32_t*)&a1;
        uh.z = *(uint32_t*)&a2; uh.w = *(uint32_t*)&a3;
        a0 = __halves2bfloat162(l[0], l[1]);
        a1 = __halves2bfloat162(l[2], l[3]);
        a2 = __halves2bfloat162(l[4], l[5]);
        a3 = __halves2bfloat162(l[6], l[7]);
        ul.x = *(uint32_t*)&a0; ul.y = *(uint32_t*)&a1;
        ul.z = *(uint32_t*)&a2; ul.w = *(uint32_t*)&a3;
    }
    ((uint4*)g_feat_hi)[(size_t)r * D16 + lane] = uh;
    ((uint4*)g_feat_lo)[(size_t)r * D16 + lane] = ul;
    if (g_winner[node] == r + 1) {
        newY4[(size_t)node * D4 + lane * 2]     = make_float4(g[0], g[1], g[2], g[3]);
        newY4[(size_t)node * D4 + lane * 2 + 1] = make_float4(g[4], g[5], g[6], g[7]);
    }
}

// ====== HMMA GEMM (3-term bf16 split) + PERSISTENT decay blocks ==============
// 782 GEMM tiles + DECAY_PERSIST grid-stride decay blocks = one wave (7/SM cap).
// The resident decay blocks loop over ALL 12500 slices -> the 400MB DRAM stream
// runs concurrently under the compute-bound GEMM instead of after it.
#define AST 24
#define SM_A_HI 0
#define SM_A_LO 3072
#define SM_B_HI 6144
#define SM_B_LO 18432
#define SM_GEMM_TOTAL 30720
#define EP_SUM  0
#define EP_SSQ  2048
#define EP_MEAN 4096
#define EP_RSTD 4352

__device__ __forceinline__ void mma_bf16(float* c, uint32_t a0, uint32_t a1,
                                         uint32_t a2, uint32_t a3,
                                         uint32_t b0, uint32_t b1) {
    asm volatile(
        "mma.sync.aligned.m16n8k16.row.col.f32.bf16.bf16.f32 "
        "{%0,%1,%2,%3}, {%4,%5,%6,%7}, {%8,%9}, {%0,%1,%2,%3};"
        : "+f"(c[0]), "+f"(c[1]), "+f"(c[2]), "+f"(c[3])
        : "r"(a0), "r"(a1), "r"(a2), "r"(a3), "r"(b0), "r"(b1));
}

__global__ __launch_bounds__(256) void k_gemm_decay(
    const float* __restrict__ bvec, const float* __restrict__ scale,
    const float* __restrict__ offset, float* __restrict__ out,
    const float4* __restrict__ y4, float4* __restrict__ newY4,
    int nsamp, int ntotal, int gemmB, int decayB) {
    __shared__ char sm[SM_GEMM_TOTAL];
    int t = threadIdx.x;
    int bk = blockIdx.x;

    if (bk >= gemmB) {
        // ---- persistent decay: grid-stride over all slices ----
        long long total = (long long)ntotal * D4;
        int nSlices = (int)((total + 1023) >> 10);
        for (int piece = bk - gemmB; piece < nSlices; piece += decayB) {
            long long i0 = (long long)piece * 1024 + t;
            int wv[4];
            long long ii[4];
#pragma unroll
            for (int j = 0; j < 4; j++) {
                ii[j] = i0 + j * 256;
                wv[j] = (ii[j] < total) ? g_winner[(int)(ii[j] >> 6)] : 1;
            }
            __syncthreads();      // all reads of this slice's winners done
#pragma unroll
            for (int j = 0; j < 4; j++)
                if (ii[j] < total && (ii[j] & 63) == 0)
                    g_winner[(int)(ii[j] >> 6)] = 0;   // self-clean for next call
#pragma unroll
            for (int j = 0; j < 4; j++) {
                if (ii[j] < total && wv[j] == 0) {
                    float4 v = y4[ii[j]];
                    v.x *= 0.9f; v.y *= 0.9f; v.z *= 0.9f; v.w *= 0.9f;
                    newY4[ii[j]] = v;
                }
            }
        }
        return;
    }

    // -------------------------- GEMM tile ------------------------------------
    int piece = bk;
    int warp = t >> 5, lane = t & 31;
    int lq = lane >> 2, lc = lane & 3;
    int wN = warp * 32;
    int rowBase = piece * 64;

    float acc[4][4][4];
#pragma unroll
    for (int i = 0; i < 4; i++)
#pragma unroll
        for (int j = 0; j < 4; j++)
#pragma unroll
            for (int q = 0; q < 4; q++) acc[i][j][q] = 0.f;

    int arow = t >> 2, ac4 = t & 3;
    int agrow = rowBase + arow;

    uint2 pAh, pAl, pBh[4], pBl[4];
    {
        pAh = make_uint2(0u, 0u); pAl = make_uint2(0u, 0u);
        if (agrow < nsamp) {
            pAh = *(const uint2*)&g_feat_hi[(size_t)agrow * D + ac4 * 4];
            pAl = *(const uint2*)&g_feat_lo[(size_t)agrow * D + ac4 * 4];
        }
#pragma unroll
        for (int j = 0; j < 4; j++) {
            int i = t + j * 256;
            int n = i >> 2, c4 = i & 3;
            pBh[j] = *(const uint2*)&g_wt_hi[(size_t)n * D + c4 * 4];
            pBl[j] = *(const uint2*)&g_wt_lo[(size_t)n * D + c4 * 4];
        }
    }

    for (int kc = 0; kc < 16; kc++) {
        *(uint2*)(sm + SM_A_HI + (arow * AST + ac4 * 4) * 2) = pAh;
        *(uint2*)(sm + SM_A_LO + (arow * AST + ac4 * 4) * 2) = pAl;
#pragma unroll
        for (int j = 0; j < 4; j++) {
            int i = t + j * 256;
            int n = i >> 2, c4 = i & 3;
            *(uint2*)(sm + SM_B_HI + (n * AST + c4 * 4) * 2) = pBh[j];
            *(uint2*)(sm + SM_B_LO + (n * AST + c4 * 4) * 2) = pBl[j];
        }
        __syncthreads();

        if (kc < 15) {
            int k0 = (kc + 1) * 16;
            pAh = make_uint2(0u, 0u); pAl = make_uint2(0u, 0u);
            if (agrow < nsamp) {
                pAh = *(const uint2*)&g_feat_hi[(size_t)agrow * D + k0 + ac4 * 4];
                pAl = *(const uint2*)&g_feat_lo[(size_t)agrow * D + k0 + ac4 * 4];
            }
#pragma unroll
            for (int j = 0; j < 4; j++) {
                int i = t + j * 256;
                int n = i >> 2, c4 = i & 3;
                pBh[j] = *(const uint2*)&g_wt_hi[(size_t)n * D + k0 + c4 * 4];
                pBl[j] = *(const uint2*)&g_wt_lo[(size_t)n * D + k0 + c4 * 4];
            }
        }

        uint32_t bh[4][2], bl[4][2];
#pragma unroll
        for (int nf = 0; nf < 4; nf++) {
            int n = wN + nf * 8 + lq;
            bh[nf][0] = *(uint32_t*)(sm + SM_B_HI + (n * AST + lc * 2) * 2);
            bh[nf][1] = *(uint32_t*)(sm + SM_B_HI + (n * AST + lc * 2 + 8) * 2);
            bl[nf][0] = *(uint32_t*)(sm + SM_B_LO + (n * AST + lc * 2) * 2);
            bl[nf][1] = *(uint32_t*)(sm + SM_B_LO + (n * AST + lc * 2 + 8) * 2);
        }
        {
            uint32_t ah[4][4];
#pragma unroll
            for (int mf = 0; mf < 4; mf++) {
                int r0 = mf * 16 + lq;
                ah[mf][0] = *(uint32_t*)(sm + SM_A_HI + (r0 * AST + lc * 2) * 2);
                ah[mf][1] = *(uint32_t*)(sm + SM_A_HI + ((r0 + 8) * AST + lc * 2) * 2);
                ah[mf][2] = *(uint32_t*)(sm + SM_A_HI + (r0 * AST + lc * 2 + 8) * 2);
                ah[mf][3] = *(uint32_t*)(sm + SM_A_HI + ((r0 + 8) * AST + lc * 2 + 8) * 2);
            }
#pragma unroll
            for (int mf = 0; mf < 4; mf++)
#pragma unroll
                for (int nf = 0; nf < 4; nf++) {
                    mma_bf16(acc[mf][nf], ah[mf][0], ah[mf][1], ah[mf][2], ah[mf][3],
                             bh[nf][0], bh[nf][1]);
                    mma_bf16(acc[mf][nf], ah[mf][0], ah[mf][1], ah[mf][2], ah[mf][3],
                             bl[nf][0], bl[nf][1]);
                }
        }
        {
            uint32_t al[4][4];
#pragma unroll
            for (int mf = 0; mf < 4; mf++) {
                int r0 = mf * 16 + lq;
                al[mf][0] = *(uint32_t*)(sm + SM_A_LO + (r0 * AST + lc * 2) * 2);
                al[mf][1] = *(uint32_t*)(sm + SM_A_LO + ((r0 + 8) * AST + lc * 2) * 2);
                al[mf][2] = *(uint32_t*)(sm + SM_A_LO + (r0 * AST + lc * 2 + 8) * 2);
                al[mf][3] = *(uint32_t*)(sm + SM_A_LO + ((r0 + 8) * AST + lc * 2 + 8) * 2);
            }
#pragma unroll
            for (int mf = 0; mf < 4; mf++)
#pragma unroll
                for (int nf = 0; nf < 4; nf++)
                    mma_bf16(acc[mf][nf], al[mf][0], al[mf][1], al[mf][2], al[mf][3],
                             bh[nf][0], bh[nf][1]);
        }
        __syncthreads();
    }

    // ---- epilogue: bias -> ELU -> cross-warp row reduce -> normalize --------
    float bb[4][2], ss[4][2], oo[4][2];
#pragma unroll
    for (int nf = 0; nf < 4; nf++) {
        int col = wN + nf * 8 + lc * 2;
        bb[nf][0] = bvec[col];   bb[nf][1] = bvec[col + 1];
        ss[nf][0] = scale[col];  ss[nf][1] = scale[col + 1];
        oo[nf][0] = offset[col]; oo[nf][1] = offset[col + 1];
    }

    float rs[4][2], rq[4][2];
#pragma unroll
    for (int mf = 0; mf < 4; mf++) { rs[mf][0] = rs[mf][1] = 0.f; rq[mf][0] = rq[mf][1] = 0.f; }
#pragma unroll
    for (int mf = 0; mf < 4; mf++)
#pragma unroll
        for (int nf = 0; nf < 4; nf++) {
            float v0 = acc[mf][nf][0] + bb[nf][0];
            float v1 = acc[mf][nf][1] + bb[nf][1];
            float v2 = acc[mf][nf][2] + bb[nf][0];
            float v3 = acc[mf][nf][3] + bb[nf][1];
            v0 = (v0 > 0.f) ? v0 : expm1f(v0);
            v1 = (v1 > 0.f) ? v1 : expm1f(v1);
            v2 = (v2 > 0.f) ? v2 : expm1f(v2);
            v3 = (v3 > 0.f) ? v3 : expm1f(v3);
            acc[mf][nf][0] = v0; acc[mf][nf][1] = v1;
            acc[mf][nf][2] = v2; acc[mf][nf][3] = v3;
            rs[mf][0] += v0 + v1; rq[mf][0] += v0 * v0 + v1 * v1;
            rs[mf][1] += v2 + v3; rq[mf][1] += v2 * v2 + v3 * v3;
        }
#pragma unroll
    for (int mf = 0; mf < 4; mf++)
#pragma unroll
        for (int h = 0; h < 2; h++) {
            rs[mf][h] += __shfl_xor_sync(0xffffffff, rs[mf][h], 1);
            rs[mf][h] += __shfl_xor_sync(0xffffffff, rs[mf][h], 2);
            rq[mf][h] += __shfl_xor_sync(0xffffffff, rq[mf][h], 1);
            rq[mf][h] += __shfl_xor_sync(0xffffffff, rq[mf][h], 2);
        }
    __syncthreads();
    float* rowsum = (float*)(sm + EP_SUM);
    float* rowssq = (float*)(sm + EP_SSQ);
    if (lc == 0) {
#pragma unroll
        for (int mf = 0; mf < 4; mf++) {
            rowsum[(mf * 16 + lq) * 8 + warp]     = rs[mf][0];
            rowssq[(mf * 16 + lq) * 8 + warp]     = rq[mf][0];
            rowsum[(mf * 16 + 8 + lq) * 8 + warp] = rs[mf][1];
            rowssq[(mf * 16 + 8 + lq) * 8 + warp] = rq[mf][1];
        }
    }
    __syncthreads();
    float* meanA = (float*)(sm + EP_MEAN);
    float* rstdA = (float*)(sm + EP_RSTD);
    if (t < 64) {
        float s = 0.f, q = 0.f;
#pragma unroll
        for (int w = 0; w < 8; w++) { s += rowsum[t * 8 + w]; q += rowssq[t * 8 + w]; }
        float mean = s * (1.f / 256.f);
        float var  = q * (1.f / 256.f) - mean * mean + 1e-9f;
        meanA[t] = mean;
        rstdA[t] = rsqrtf(var);
    }
    __syncthreads();

#pragma unroll
    for (int mf = 0; mf < 4; mf++) {
        int rl = mf * 16 + lq;
        int rh = rl + 8;
        float mL = meanA[rl], rL = rstdA[rl];
        float mH = meanA[rh], rH = rstdA[rh];
        int gl = rowBase + rl, gh = rowBase + rh;
#pragma unroll
        for (int nf = 0; nf < 4; nf++) {
            int col = wN + nf * 8 + lc * 2;
            if (gl < nsamp) {
                float2 p;
                p.x = (acc[mf][nf][0] - mL) * ss[nf][0] * rL + oo[nf][0];
                p.y = (acc[mf][nf][1] - mL) * ss[nf][1] * rL + oo[nf][1];
                *(float2*)(out + (size_t)gl * D + col) = p;
            }
            if (gh < nsamp) {
                float2 p;
                p.x = (acc[mf][nf][2] - mH) * ss[nf][0] * rH + oo[nf][0];
                p.y = (acc[mf][nf][3] - mH) * ss[nf][1] * rH + oo[nf][1];
                *(float2*)(out + (size_t)gh * D + col) = p;
            }
        }
    }
}

// -----------------------------------------------------------------------------
extern "C" void kernel_launch(void* const* d_in, const int* in_sizes, int n_in,
                              void* d_out, int out_size) {
    const float* x        = (const float*)d_in[0];
    const int*   adj_row  = (const int*)d_in[1];
    const int*   adj_col  = (const int*)d_in[2];
    const float* adj_val  = (const float*)d_in[3];
    const int*   nodes    = (const int*)d_in[4];
    const float* y_buf    = (const float*)d_in[5];
    const float* W        = (const float*)d_in[6];
    const float* b        = (const float*)d_in[7];
    const float* scale    = (const float*)d_in[8];
    const float* offset   = (const float*)d_in[9];

    int E      = in_sizes[1];
    int nsamp  = in_sizes[4];
    int nsrc   = in_sizes[0] / D;
    int ntotal = in_sizes[5] / D;

    float* out  = (float*)d_out;
    float* newY = out + (size_t)nsamp * D;

    int G = (nsamp + SCAN_EPB - 1) / SCAN_EPB;
    int spmmB  = (nsamp + 7) / 8;
    int gemmB  = (nsamp + 63) / 64;
    int decayB = DECAY_PERSIST;
    int convB  = (nsrc * D4 + 1023) / 1024;
    int wB     = (D * D + 255) / 256;
    int histB  = (E + 255) / 256;

    k_prep<<<convB + wB + histB, 256>>>(x, W, adj_row, E, nodes, nsamp, nsrc, convB, wB);
    k_scan<<<G, SCAN_TPB>>>(nsamp, E);
    k_scatter<<<(E + 255) / 256, 256>>>(adj_row, adj_col, adj_val, E, nsamp);
    k_spmm<<<spmmB, 256>>>(nodes, (const float4*)y_buf, (float4*)newY, nsamp);
    k_gemm_decay<<<gemmB + decayB, 256>>>(b, scale, offset, out,
                                          (const float4*)y_buf, (float4*)newY,
                                          nsamp, ntotal, gemmB, decayB);
}

// round 10
// speedup vs baseline: 1.4481x; 1.4481x over previous
#include <cuda_runtime.h>
#include <cuda_bf16.h>
#include <math.h>
#include <cstdint>

#define D     256
#define D4    64
#define D16   32                     // uint4 per 256-bf16 row
#define MAX_NSAMP  50000
#define MAX_NSRC   50000
#define MAX_NTOTAL 200000
#define MAX_E      1600000
#define SCAN_TPB   256
#define SCAN_EPB   2048

// ---------------- scratch (static device globals; no allocation) -------------
// Self-cleaning invariants (valid at entry of every kernel_launch call):
//   g_hist == 0 (zeroed by k_scatter), g_cursor == 0 (zeroed by k_scan),
//   g_winner == 0 (zeroed at end of k_gemm_mma; encoding: winner = idx+1, 0 = empty)
__device__ __nv_bfloat16 g_xbf[MAX_NSRC * D];
__device__ __nv_bfloat16 g_feat_hi[MAX_NSAMP * D];
__device__ __nv_bfloat16 g_feat_lo[MAX_NSAMP * D];
__device__ __nv_bfloat16 g_wt_hi[D * D];             // W^T hi  [n][k]
__device__ __nv_bfloat16 g_wt_lo[D * D];             // W^T lo
__device__ int   g_hist[MAX_NSAMP];
__device__ int   g_cursor[MAX_NSAMP];
__device__ int   g_rowStart[MAX_NSAMP + 1];
__device__ int   g_winner[MAX_NTOTAL];
__device__ int2  g_edge[MAX_E];

// ================= prep: x->bf16, W^T split, hist, winner ====================
__global__ void k_prep(const float* __restrict__ x, const float* __restrict__ W,
                       const int* __restrict__ row, int E,
                       const int* __restrict__ nodes, int nsamp,
                       int nsrc, int convB, int wB) {
    int b = blockIdx.x;
    int t = threadIdx.x;
    if (b < convB) {
        long long total = (long long)nsrc * D4;
        long long i0 = (long long)b * 1024 + t;
        const float4* x4 = (const float4*)x;
#pragma unroll
        for (int j = 0; j < 4; j++) {
            long long i = i0 + j * 256;
            if (i < total) {
                float4 v = x4[i];
                __nv_bfloat162 p0 = __floats2bfloat162_rn(v.x, v.y);
                __nv_bfloat162 p1 = __floats2bfloat162_rn(v.z, v.w);
                uint2 u;
                u.x = *(uint32_t*)&p0;
                u.y = *(uint32_t*)&p1;
                ((uint2*)g_xbf)[i] = u;
            }
        }
        return;
    }
    if (b < convB + wB) {
        int i = (b - convB) * 256 + t;
        if (i < D * D) {
            int k = i >> 8, n = i & 255;
            float w = W[k * D + n];
            __nv_bfloat16 hi = __float2bfloat16_rn(w);
            __nv_bfloat16 lo = __float2bfloat16_rn(w - __bfloat162float(hi));
            g_wt_hi[n * D + k] = hi;
            g_wt_lo[n * D + k] = lo;
        }
        return;
    }
    int i = (b - convB - wB) * 256 + t;
    if (i < E) atomicAdd(&g_hist[row[i]], 1);
    if (i < nsamp) atomicMax(&g_winner[nodes[i]], i + 1);   // 0 = empty
}

// ===== single-kernel scan: each block sums its own prefix (G~25, cheap) ======
__global__ __launch_bounds__(SCAN_TPB) void k_scan(int n, int E) {
    __shared__ int sred[SCAN_TPB / 32];
    __shared__ int ws[SCAN_TPB / 32];
    int t = threadIdx.x, lane = t & 31, w = t >> 5;
    int tileStart = blockIdx.x * SCAN_EPB;

    int ps = 0;
    for (int i = t; i < tileStart; i += SCAN_TPB) ps += g_hist[i];
#pragma unroll
    for (int o = 16; o > 0; o >>= 1) ps += __shfl_xor_sync(0xffffffff, ps, o);
    if (lane == 0) sred[w] = ps;

    int base = tileStart + t * 8;
    int v[8], sum = 0;
#pragma unroll
    for (int j = 0; j < 8; j++) {
        int idx = base + j;
        v[j] = (idx < n) ? g_hist[idx] : 0;
        if (idx < n) g_cursor[idx] = 0;
        sum += v[j];
    }
    int x = sum;
#pragma unroll
    for (int o = 1; o < 32; o <<= 1) {
        int y = __shfl_up_sync(0xffffffff, x, o);
        if (lane >= o) x += y;
    }
    if (lane == 31) ws[w] = x;
    __syncthreads();
    if (t == 0) {
        int total = 0;
#pragma unroll
        for (int i = 0; i < SCAN_TPB / 32; i++) total += sred[i];
        int r = total;
#pragma unroll
        for (int i = 0; i < SCAN_TPB / 32; i++) { int q = ws[i]; ws[i] = r; r += q; }
    }
    __syncthreads();
    int run = ws[w] + (x - sum);
#pragma unroll
    for (int j = 0; j < 8; j++) {
        int idx = base + j;
        if (idx < n) g_rowStart[idx] = run;
        run += v[j];
    }
    if (blockIdx.x == 0 && t == 0) g_rowStart[n] = E;
}

// ============ scatter edges into row-sorted order (+ zero hist) ==============
__global__ void k_scatter(const int* __restrict__ row, const int* __restrict__ col,
                          const float* __restrict__ val, int E, int nsamp) {
    int i = blockIdx.x * blockDim.x + threadIdx.x;
    if (i < nsamp) g_hist[i] = 0;               // clean for next call
    if (i < E) {
        int r = row[i];
        int p = g_rowStart[r] + atomicAdd(&g_cursor[r], 1);
        int2 e;
        e.x = col[i];
        e.y = __float_as_int(val[i]);
        g_edge[p] = e;
    }
}

// ====== fused SpMM (warp-per-row, 16B gathers, 8-edge unroll) + decay ========
// R5 config (best measured): even/odd interleaved spmm/decay blocks.
__global__ __launch_bounds__(256) void k_spmm_decay(
    const int* __restrict__ nodes,
    const float4* __restrict__ y4, float4* __restrict__ newY4,
    int nsamp, int ntotal, int spmmB, int decayB) {
    int b = blockIdx.x;
    int t = threadIdx.x;
    int mn = min(spmmB, decayB);
    int nInter = 2 * mn;
    int type, piece;
    if (b < nInter) { type = b & 1; piece = b >> 1; }
    else { type = (spmmB > decayB) ? 0 : 1; piece = mn + (b - nInter); }

    if (type == 1) {
        long long total = (long long)ntotal * D4;
        long long i0 = (long long)piece * 1024 + t;
#pragma unroll
        for (int j = 0; j < 4; j++) {
            long long i = i0 + j * 256;
            if (i < total) {
                int rrow = (int)(i >> 6);
                if (g_winner[rrow] == 0) {
                    float4 v = y4[i];
                    v.x *= 0.9f; v.y *= 0.9f; v.z *= 0.9f; v.w *= 0.9f;
                    newY4[i] = v;
                }
            }
        }
        return;
    }

    // SpMM: one warp per row, lane owns 8 bf16 (one uint4) of the row
    int warp = t >> 5, lane = t & 31;
    int r = piece * 8 + warp;
    if (r >= nsamp) return;
    int e = g_rowStart[r];
    int end = g_rowStart[r + 1];
    const uint4* xb = (const uint4*)g_xbf;
    float acc[8];
#pragma unroll
    for (int q = 0; q < 8; q++) acc[q] = 0.f;

#pragma unroll 1
    for (; e + 8 <= end; e += 8) {
        uint4 u[8];
        float vv[8];
#pragma unroll
        for (int j = 0; j < 8; j++) {
            int2 ed = g_edge[e + j];
            vv[j] = __int_as_float(ed.y);
            u[j] = xb[(size_t)ed.x * D16 + lane];
        }
#pragma unroll
        for (int j = 0; j < 8; j++) {
            float2 p0 = __bfloat1622float2(*(__nv_bfloat162*)&u[j].x);
            float2 p1 = __bfloat1622float2(*(__nv_bfloat162*)&u[j].y);
            float2 p2 = __bfloat1622float2(*(__nv_bfloat162*)&u[j].z);
            float2 p3 = __bfloat1622float2(*(__nv_bfloat162*)&u[j].w);
            float v = vv[j];
            acc[0] = fmaf(v, p0.x, acc[0]); acc[1] = fmaf(v, p0.y, acc[1]);
            acc[2] = fmaf(v, p1.x, acc[2]); acc[3] = fmaf(v, p1.y, acc[3]);
            acc[4] = fmaf(v, p2.x, acc[4]); acc[5] = fmaf(v, p2.y, acc[5]);
            acc[6] = fmaf(v, p3.x, acc[6]); acc[7] = fmaf(v, p3.y, acc[7]);
        }
    }
    for (; e < end; e++) {
        int2 ed = g_edge[e];
        float v = __int_as_float(ed.y);
        uint4 u = xb[(size_t)ed.x * D16 + lane];
        float2 p0 = __bfloat1622float2(*(__nv_bfloat162*)&u.x);
        float2 p1 = __bfloat1622float2(*(__nv_bfloat162*)&u.y);
        float2 p2 = __bfloat1622float2(*(__nv_bfloat162*)&u.z);
        float2 p3 = __bfloat1622float2(*(__nv_bfloat162*)&u.w);
        acc[0] = fmaf(v, p0.x, acc[0]); acc[1] = fmaf(v, p0.y, acc[1]);
        acc[2] = fmaf(v, p1.x, acc[2]); acc[3] = fmaf(v, p1.y, acc[3]);
        acc[4] = fmaf(v, p2.x, acc[4]); acc[5] = fmaf(v, p2.y, acc[5]);
        acc[6] = fmaf(v, p3.x, acc[6]); acc[7] = fmaf(v, p3.y, acc[7]);
    }

    int node = nodes[r];
    float4 y0 = y4[(size_t)node * D4 + lane * 2];
    float4 y1 = y4[(size_t)node * D4 + lane * 2 + 1];
    float g[8];
    g[0] = fmaf(0.1f, acc[0], 0.9f * y0.x);
    g[1] = fmaf(0.1f, acc[1], 0.9f * y0.y);
    g[2] = fmaf(0.1f, acc[2], 0.9f * y0.z);
    g[3] = fmaf(0.1f, acc[3], 0.9f * y0.w);
    g[4] = fmaf(0.1f, acc[4], 0.9f * y1.x);
    g[5] = fmaf(0.1f, acc[5], 0.9f * y1.y);
    g[6] = fmaf(0.1f, acc[6], 0.9f * y1.z);
    g[7] = fmaf(0.1f, acc[7], 0.9f * y1.w);

    uint4 uh, ul;
    {
        __nv_bfloat16 h[8], l[8];
#pragma unroll
        for (int q = 0; q < 8; q++) {
            h[q] = __float2bfloat16_rn(g[q]);
            l[q] = __float2bfloat16_rn(g[q] - __bfloat162float(h[q]));
        }
        __nv_bfloat162 a0 = __halves2bfloat162(h[0], h[1]);
        __nv_bfloat162 a1 = __halves2bfloat162(h[2], h[3]);
        __nv_bfloat162 a2 = __halves2bfloat162(h[4], h[5]);
        __nv_bfloat162 a3 = __halves2bfloat162(h[6], h[7]);
        uh.x = *(uint32_t*)&a0; uh.y = *(uint32_t*)&a1;
        uh.z = *(uint32_t*)&a2; uh.w = *(uint32_t*)&a3;
        a0 = __halves2bfloat162(l[0], l[1]);
        a1 = __halves2bfloat162(l[2], l[3]);
        a2 = __halves2bfloat162(l[4], l[5]);
        a3 = __halves2bfloat162(l[6], l[7]);
        ul.x = *(uint32_t*)&a0; ul.y = *(uint32_t*)&a1;
        ul.z = *(uint32_t*)&a2; ul.w = *(uint32_t*)&a3;
    }
    ((uint4*)g_feat_hi)[(size_t)r * D16 + lane] = uh;
    ((uint4*)g_feat_lo)[(size_t)r * D16 + lane] = ul;
    if (g_winner[node] == r + 1) {
        newY4[(size_t)node * D4 + lane * 2]     = make_float4(g[0], g[1], g[2], g[3]);
        newY4[(size_t)node * D4 + lane * 2 + 1] = make_float4(g[4], g[5], g[6], g[7]);
    }
}

// ========== HMMA GEMM m16n8k16 bf16 3-term split, ldmatrix fragments =========
#define AST 24
#define SM_A_HI 0
#define SM_A_LO 3072
#define SM_B_HI 6144
#define SM_B_LO 18432
#define SM_GEMM_TOTAL 30720
#define EP_SUM  0
#define EP_SSQ  2048
#define EP_MEAN 4096
#define EP_RSTD 4352

__device__ __forceinline__ void mma_bf16(float* c, uint32_t a0, uint32_t a1,
                                         uint32_t a2, uint32_t a3,
                                         uint32_t b0, uint32_t b1) {
    asm volatile(
        "mma.sync.aligned.m16n8k16.row.col.f32.bf16.bf16.f32 "
        "{%0,%1,%2,%3}, {%4,%5,%6,%7}, {%8,%9}, {%0,%1,%2,%3};"
        : "+f"(c[0]), "+f"(c[1]), "+f"(c[2]), "+f"(c[3])
        : "r"(a0), "r"(a1), "r"(a2), "r"(a3), "r"(b0), "r"(b1));
}

#define LDMX4(r0, r1, r2, r3, addr) \
    asm volatile("ldmatrix.sync.aligned.m8n8.x4.shared.b16 {%0,%1,%2,%3}, [%4];" \
        : "=r"(r0), "=r"(r1), "=r"(r2), "=r"(r3) : "r"(addr))

__global__ __launch_bounds__(256) void k_gemm_mma(
    const float* __restrict__ bvec, const float* __restrict__ scale,
    const float* __restrict__ offset, float* __restrict__ out,
    int nsamp, int ntotal) {
    __shared__ char sm[SM_GEMM_TOTAL];
    int t = threadIdx.x;
    int warp = t >> 5, lane = t & 31;
    int lq = lane >> 2, lc = lane & 3;
    int wN = warp * 32;
    int rowBase = blockIdx.x * 64;

    float acc[4][4][4];
#pragma unroll
    for (int i = 0; i < 4; i++)
#pragma unroll
        for (int j = 0; j < 4; j++)
#pragma unroll
            for (int q = 0; q < 4; q++) acc[i][j][q] = 0.f;

    int arow = t >> 2, ac4 = t & 3;
    int agrow = rowBase + arow;

    // ldmatrix per-lane address components (bytes)
    uint32_t sbase = (uint32_t)__cvta_generic_to_shared(sm);
    // A x4: m0 rows0-7 k0 | m1 rows8-15 k0 | m2 rows0-7 k8 | m3 rows8-15 k8
    uint32_t aLaneOff = ((((lane >> 3) & 1) * 8 + (lane & 7)) * AST + (lane >> 4) * 8) * 2;
    // B x4: m0 nf0 k0 | m1 nf0 k8 | m2 nf1 k0 | m3 nf1 k8
    uint32_t bLaneOff = (((lane >> 4) * 8 + (lane & 7)) * AST + ((lane >> 3) & 1) * 8) * 2;
    uint32_t aHiAddr = sbase + SM_A_HI + aLaneOff;
    uint32_t aLoAddr = sbase + SM_A_LO + aLaneOff;
    uint32_t bHiAddr = sbase + SM_B_HI + bLaneOff + (uint32_t)(wN * AST * 2);
    uint32_t bLoAddr = sbase + SM_B_LO + bLaneOff + (uint32_t)(wN * AST * 2);

    uint2 pAh, pAl, pBh[4], pBl[4];
    {
        pAh = make_uint2(0u, 0u); pAl = make_uint2(0u, 0u);
        if (agrow < nsamp) {
            pAh = *(const uint2*)&g_feat_hi[(size_t)agrow * D + ac4 * 4];
            pAl = *(const uint2*)&g_feat_lo[(size_t)agrow * D + ac4 * 4];
        }
#pragma unroll
        for (int j = 0; j < 4; j++) {
            int i = t + j * 256;
            int n = i >> 2, c4 = i & 3;
            pBh[j] = *(const uint2*)&g_wt_hi[(size_t)n * D + c4 * 4];
            pBl[j] = *(const uint2*)&g_wt_lo[(size_t)n * D + c4 * 4];
        }
    }

    for (int kc = 0; kc < 16; kc++) {
        *(uint2*)(sm + SM_A_HI + (arow * AST + ac4 * 4) * 2) = pAh;
        *(uint2*)(sm + SM_A_LO + (arow * AST + ac4 * 4) * 2) = pAl;
#pragma unroll
        for (int j = 0; j < 4; j++) {
            int i = t + j * 256;
            int n = i >> 2, c4 = i & 3;
            *(uint2*)(sm + SM_B_HI + (n * AST + c4 * 4) * 2) = pBh[j];
            *(uint2*)(sm + SM_B_LO + (n * AST + c4 * 4) * 2) = pBl[j];
        }
        __syncthreads();

        if (kc < 15) {
            int k0 = (kc + 1) * 16;
            pAh = make_uint2(0u, 0u); pAl = make_uint2(0u, 0u);
            if (agrow < nsamp) {
                pAh = *(const uint2*)&g_feat_hi[(size_t)agrow * D + k0 + ac4 * 4];
                pAl = *(const uint2*)&g_feat_lo[(size_t)agrow * D + k0 + ac4 * 4];
            }
#pragma unroll
            for (int j = 0; j < 4; j++) {
                int i = t + j * 256;
                int n = i >> 2, c4 = i & 3;
                pBh[j] = *(const uint2*)&g_wt_hi[(size_t)n * D + k0 + c4 * 4];
                pBl[j] = *(const uint2*)&g_wt_lo[(size_t)n * D + k0 + c4 * 4];
            }
        }

        // B fragments via ldmatrix.x4 (one x4 covers two n-tiles)
        uint32_t bh[4][2], bl[4][2];
        LDMX4(bh[0][0], bh[0][1], bh[1][0], bh[1][1], bHiAddr);
        LDMX4(bh[2][0], bh[2][1], bh[3][0], bh[3][1], bHiAddr + 16 * AST * 2);
        LDMX4(bl[0][0], bl[0][1], bl[1][0], bl[1][1], bLoAddr);
        LDMX4(bl[2][0], bl[2][1], bl[3][0], bl[3][1], bLoAddr + 16 * AST * 2);
        {
            uint32_t ah[4][4];
#pragma unroll
            for (int mf = 0; mf < 4; mf++)
                LDMX4(ah[mf][0], ah[mf][1], ah[mf][2], ah[mf][3],
                      aHiAddr + mf * (16 * AST * 2));
#pragma unroll
            for (int mf = 0; mf < 4; mf++)
#pragma unroll
                for (int nf = 0; nf < 4; nf++) {
                    mma_bf16(acc[mf][nf], ah[mf][0], ah[mf][1], ah[mf][2], ah[mf][3],
                             bh[nf][0], bh[nf][1]);
                    mma_bf16(acc[mf][nf], ah[mf][0], ah[mf][1], ah[mf][2], ah[mf][3],
                             bl[nf][0], bl[nf][1]);
                }
        }
        {
            uint32_t al[4][4];
#pragma unroll
            for (int mf = 0; mf < 4; mf++)
                LDMX4(al[mf][0], al[mf][1], al[mf][2], al[mf][3],
                      aLoAddr + mf * (16 * AST * 2));
#pragma unroll
            for (int mf = 0; mf < 4; mf++)
#pragma unroll
                for (int nf = 0; nf < 4; nf++)
                    mma_bf16(acc[mf][nf], al[mf][0], al[mf][1], al[mf][2], al[mf][3],
                             bh[nf][0], bh[nf][1]);
        }
        __syncthreads();
    }

    // ---- epilogue: bias -> ELU -> cross-warp row reduce -> normalize --------
    float bb[4][2], ss[4][2], oo[4][2];
#pragma unroll
    for (int nf = 0; nf < 4; nf++) {
        int col = wN + nf * 8 + lc * 2;
        bb[nf][0] = bvec[col];   bb[nf][1] = bvec[col + 1];
        ss[nf][0] = scale[col];  ss[nf][1] = scale[col + 1];
        oo[nf][0] = offset[col]; oo[nf][1] = offset[col + 1];
    }

    float rs[4][2], rq[4][2];
#pragma unroll
    for (int mf = 0; mf < 4; mf++) { rs[mf][0] = rs[mf][1] = 0.f; rq[mf][0] = rq[mf][1] = 0.f; }
#pragma unroll
    for (int mf = 0; mf < 4; mf++)
#pragma unroll
        for (int nf = 0; nf < 4; nf++) {
            float v0 = acc[mf][nf][0] + bb[nf][0];
            float v1 = acc[mf][nf][1] + bb[nf][1];
            float v2 = acc[mf][nf][2] + bb[nf][0];
            float v3 = acc[mf][nf][3] + bb[nf][1];
            v0 = (v0 > 0.f) ? v0 : expm1f(v0);
            v1 = (v1 > 0.f) ? v1 : expm1f(v1);
            v2 = (v2 > 0.f) ? v2 : expm1f(v2);
            v3 = (v3 > 0.f) ? v3 : expm1f(v3);
            acc[mf][nf][0] = v0; acc[mf][nf][1] = v1;
            acc[mf][nf][2] = v2; acc[mf][nf][3] = v3;
            rs[mf][0] += v0 + v1; rq[mf][0] += v0 * v0 + v1 * v1;
            rs[mf][1] += v2 + v3; rq[mf][1] += v2 * v2 + v3 * v3;
        }
#pragma unroll
    for (int mf = 0; mf < 4; mf++)
#pragma unroll
        for (int h = 0; h < 2; h++) {
            rs[mf][h] += __shfl_xor_sync(0xffffffff, rs[mf][h], 1);
            rs[mf][h] += __shfl_xor_sync(0xffffffff, rs[mf][h], 2);
            rq[mf][h] += __shfl_xor_sync(0xffffffff, rq[mf][h], 1);
            rq[mf][h] += __shfl_xor_sync(0xffffffff, rq[mf][h], 2);
        }
    __syncthreads();
    float* rowsum = (float*)(sm + EP_SUM);
    float* rowssq = (float*)(sm + EP_SSQ);
    if (lc == 0) {
#pragma unroll
        for (int mf = 0; mf < 4; mf++) {
            rowsum[(mf * 16 + lq) * 8 + warp]     = rs[mf][0];
            rowssq[(mf * 16 + lq) * 8 + warp]     = rq[mf][0];
            rowsum[(mf * 16 + 8 + lq) * 8 + warp] = rs[mf][1];
            rowssq[(mf * 16 + 8 + lq) * 8 + warp] = rq[mf][1];
        }
    }
    __syncthreads();
    float* meanA = (float*)(sm + EP_MEAN);
    float* rstdA = (float*)(sm + EP_RSTD);
    if (t < 64) {
        float s = 0.f, q = 0.f;
#pragma unroll
        for (int w = 0; w < 8; w++) { s += rowsum[t * 8 + w]; q += rowssq[t * 8 + w]; }
        float mean = s * (1.f / 256.f);
        float var  = q * (1.f / 256.f) - mean * mean + 1e-9f;
        meanA[t] = mean;
        rstdA[t] = rsqrtf(var);
    }
    __syncthreads();

#pragma unroll
    for (int mf = 0; mf < 4; mf++) {
        int rl = mf * 16 + lq;
        int rh = rl + 8;
        float mL = meanA[rl], rL = rstdA[rl];
        float mH = meanA[rh], rH = rstdA[rh];
        int gl = rowBase + rl, gh = rowBase + rh;
#pragma unroll
        for (int nf = 0; nf < 4; nf++) {
            int col = wN + nf * 8 + lc * 2;
            if (gl < nsamp) {
                float2 p;
                p.x = (acc[mf][nf][0] - mL) * ss[nf][0] * rL + oo[nf][0];
                p.y = (acc[mf][nf][1] - mL) * ss[nf][1] * rL + oo[nf][1];
                *(float2*)(out + (size_t)gl * D + col) = p;
            }
            if (gh < nsamp) {
                float2 p;
                p.x = (acc[mf][nf][2] - mH) * ss[nf][0] * rH + oo[nf][0];
                p.y = (acc[mf][nf][3] - mH) * ss[nf][1] * rH + oo[nf][1];
                *(float2*)(out + (size_t)gh * D + col) = p;
            }
        }
    }

    // reset winner for next invocation (last kernel in the pipeline)
    for (int gi = blockIdx.x * 256 + t; gi < ntotal; gi += gridDim.x * 256)
        g_winner[gi] = 0;
}

// -----------------------------------------------------------------------------
extern "C" void kernel_launch(void* const* d_in, const int* in_sizes, int n_in,
                              void* d_out, int out_size) {
    const float* x        = (const float*)d_in[0];
    const int*   adj_row  = (const int*)d_in[1];
    const int*   adj_col  = (const int*)d_in[2];
    const float* adj_val  = (const float*)d_in[3];
    const int*   nodes    = (const int*)d_in[4];
    const float* y_buf    = (const float*)d_in[5];
    const float* W        = (const float*)d_in[6];
    const float* b        = (const float*)d_in[7];
    const float* scale    = (const float*)d_in[8];
    const float* offset   = (const float*)d_in[9];

    int E      = in_sizes[1];
    int nsamp  = in_sizes[4];
    int nsrc   = in_sizes[0] / D;
    int ntotal = in_sizes[5] / D;

    float* out  = (float*)d_out;
    float* newY = out + (size_t)nsamp * D;

    int G = (nsamp + SCAN_EPB - 1) / SCAN_EPB;
    int spmmB  = (nsamp + 7) / 8;
    int decayB = (ntotal * D4 + 1023) / 1024;
    int convB  = (nsrc * D4 + 1023) / 1024;
    int wB     = (D * D + 255) / 256;
    int histB  = (E + 255) / 256;

    k_prep<<<convB + wB + histB, 256>>>(x, W, adj_row, E, nodes, nsamp, nsrc, convB, wB);
    k_scan<<<G, SCAN_TPB>>>(nsamp, E);
    k_scatter<<<(E + 255) / 256, 256>>>(adj_row, adj_col, adj_val, E, nsamp);
    k_spmm_decay<<<spmmB + decayB, 256>>>(nodes, (const float4*)y_buf, (float4*)newY,
                                          nsamp, ntotal, spmmB, decayB);
    k_gemm_mma<<<(nsamp + 63) / 64, 256>>>(b, scale, offset, out, nsamp, ntotal);
}

// round 11
// speedup vs baseline: 1.4763x; 1.0194x over previous
#include <cuda_runtime.h>
#include <cuda_bf16.h>
#include <math.h>
#include <cstdint>

#define D     256
#define D4    64
#define D16   32                     // uint4 per 256-bf16 row
#define MAX_NSAMP  50000
#define MAX_NSRC   50000
#define MAX_NTOTAL 200000
#define MAX_E      1600000
#define SCAN_TPB   256
#define SCAN_EPB   2048

// ---------------- scratch (static device globals; no allocation) -------------
// Self-cleaning invariants (valid at entry of every kernel_launch call):
//   g_hist == 0 (zeroed by k_scatter), g_cursor == 0 (zeroed by k_scan),
//   g_winner == 0 (zeroed at end of k_gemm_mma; encoding: winner = idx+1, 0 = empty)
__device__ __nv_bfloat16 g_xbf[MAX_NSRC * D];
__device__ __nv_bfloat16 g_feat_hi[MAX_NSAMP * D];
__device__ __nv_bfloat16 g_feat_lo[MAX_NSAMP * D];
__device__ __nv_bfloat16 g_wt_hi[D * D];             // W^T hi  [n][k]
__device__ __nv_bfloat16 g_wt_lo[D * D];             // W^T lo
__device__ int   g_hist[MAX_NSAMP];
__device__ int   g_cursor[MAX_NSAMP];
__device__ int   g_rowStart[MAX_NSAMP + 1];
__device__ int   g_winner[MAX_NTOTAL];
__device__ int2  g_edge[MAX_E];

// ================= prep: x->bf16, W^T split, hist, winner ====================
__global__ void k_prep(const float* __restrict__ x, const float* __restrict__ W,
                       const int* __restrict__ row, int E,
                       const int* __restrict__ nodes, int nsamp,
                       int nsrc, int convB, int wB) {
    int b = blockIdx.x;
    int t = threadIdx.x;
    if (b < convB) {
        long long total = (long long)nsrc * D4;
        long long i0 = (long long)b * 1024 + t;
        const float4* x4 = (const float4*)x;
#pragma unroll
        for (int j = 0; j < 4; j++) {
            long long i = i0 + j * 256;
            if (i < total) {
                float4 v = x4[i];
                __nv_bfloat162 p0 = __floats2bfloat162_rn(v.x, v.y);
                __nv_bfloat162 p1 = __floats2bfloat162_rn(v.z, v.w);
                uint2 u;
                u.x = *(uint32_t*)&p0;
                u.y = *(uint32_t*)&p1;
                ((uint2*)g_xbf)[i] = u;
            }
        }
        return;
    }
    if (b < convB + wB) {
        int i = (b - convB) * 256 + t;
        if (i < D * D) {
            int k = i >> 8, n = i & 255;
            float w = W[k * D + n];
            __nv_bfloat16 hi = __float2bfloat16_rn(w);
            __nv_bfloat16 lo = __float2bfloat16_rn(w - __bfloat162float(hi));
            g_wt_hi[n * D + k] = hi;
            g_wt_lo[n * D + k] = lo;
        }
        return;
    }
    int i = (b - convB - wB) * 256 + t;
    if (i < E) atomicAdd(&g_hist[row[i]], 1);
    if (i < nsamp) atomicMax(&g_winner[nodes[i]], i + 1);   // 0 = empty
}

// ===== single-kernel scan: each block sums its own prefix (G~25, cheap) ======
__global__ __launch_bounds__(SCAN_TPB) void k_scan(int n, int E) {
    __shared__ int sred[SCAN_TPB / 32];
    __shared__ int ws[SCAN_TPB / 32];
    int t = threadIdx.x, lane = t & 31, w = t >> 5;
    int tileStart = blockIdx.x * SCAN_EPB;

    int ps = 0;
    for (int i = t; i < tileStart; i += SCAN_TPB) ps += g_hist[i];
#pragma unroll
    for (int o = 16; o > 0; o >>= 1) ps += __shfl_xor_sync(0xffffffff, ps, o);
    if (lane == 0) sred[w] = ps;

    int base = tileStart + t * 8;
    int v[8], sum = 0;
#pragma unroll
    for (int j = 0; j < 8; j++) {
        int idx = base + j;
        v[j] = (idx < n) ? g_hist[idx] : 0;
        if (idx < n) g_cursor[idx] = 0;
        sum += v[j];
    }
    int x = sum;
#pragma unroll
    for (int o = 1; o < 32; o <<= 1) {
        int y = __shfl_up_sync(0xffffffff, x, o);
        if (lane >= o) x += y;
    }
    if (lane == 31) ws[w] = x;
    __syncthreads();
    if (t == 0) {
        int total = 0;
#pragma unroll
        for (int i = 0; i < SCAN_TPB / 32; i++) total += sred[i];
        int r = total;
#pragma unroll
        for (int i = 0; i < SCAN_TPB / 32; i++) { int q = ws[i]; ws[i] = r; r += q; }
    }
    __syncthreads();
    int run = ws[w] + (x - sum);
#pragma unroll
    for (int j = 0; j < 8; j++) {
        int idx = base + j;
        if (idx < n) g_rowStart[idx] = run;
        run += v[j];
    }
    if (blockIdx.x == 0 && t == 0) g_rowStart[n] = E;
}

// ============ scatter edges into row-sorted order (+ zero hist) ==============
__global__ void k_scatter(const int* __restrict__ row, const int* __restrict__ col,
                          const float* __restrict__ val, int E, int nsamp) {
    int i = blockIdx.x * blockDim.x + threadIdx.x;
    if (i < nsamp) g_hist[i] = 0;               // clean for next call
    if (i < E) {
        int r = row[i];
        int p = g_rowStart[r] + atomicAdd(&g_cursor[r], 1);
        int2 e;
        e.x = col[i];
        e.y = __float_as_int(val[i]);
        g_edge[p] = e;
    }
}

// ====== fused SpMM (warp-per-row) + decay (8x batched, phase-separated) ======
// R5 interleave; decay now loads 8 winners, then 8 predicated y-loads, then 8
// stores -> MLP ~8 on the DRAM stream instead of dependent load-branch-load.
__global__ __launch_bounds__(256) void k_spmm_decay(
    const int* __restrict__ nodes,
    const float4* __restrict__ y4, float4* __restrict__ newY4,
    int nsamp, int ntotal, int spmmB, int decayB) {
    int b = blockIdx.x;
    int t = threadIdx.x;
    int mn = min(spmmB, decayB);
    int nInter = 2 * mn;
    int type, piece;
    if (b < nInter) { type = b & 1; piece = b >> 1; }
    else { type = (spmmB > decayB) ? 0 : 1; piece = mn + (b - nInter); }

    if (type == 1) {
        int total = ntotal * D4;                 // fits int (12.8M)
        int i0 = piece * 2048 + t;
        int ii[8], wv[8];
#pragma unroll
        for (int j = 0; j < 8; j++) {
            ii[j] = i0 + j * 256;
            wv[j] = (ii[j] < total) ? g_winner[ii[j] >> 6] : 1;
        }
        float4 v[8];
#pragma unroll
        for (int j = 0; j < 8; j++)
            if (ii[j] < total && wv[j] == 0) v[j] = y4[ii[j]];
#pragma unroll
        for (int j = 0; j < 8; j++)
            if (ii[j] < total && wv[j] == 0) {
                float4 o;
                o.x = v[j].x * 0.9f; o.y = v[j].y * 0.9f;
                o.z = v[j].z * 0.9f; o.w = v[j].w * 0.9f;
                newY4[ii[j]] = o;
            }
        return;
    }

    // SpMM: one warp per row, lane owns 8 bf16 (one uint4) of the row
    int warp = t >> 5, lane = t & 31;
    int r = piece * 8 + warp;
    if (r >= nsamp) return;
    int e = g_rowStart[r];
    int end = g_rowStart[r + 1];
    const uint4* xb = (const uint4*)g_xbf;
    float acc[8];
#pragma unroll
    for (int q = 0; q < 8; q++) acc[q] = 0.f;

#pragma unroll 1
    for (; e + 8 <= end; e += 8) {
        uint4 u[8];
        float vv[8];
#pragma unroll
        for (int j = 0; j < 8; j++) {
            int2 ed = g_edge[e + j];
            vv[j] = __int_as_float(ed.y);
            u[j] = xb[(size_t)ed.x * D16 + lane];
        }
#pragma unroll
        for (int j = 0; j < 8; j++) {
            float2 p0 = __bfloat1622float2(*(__nv_bfloat162*)&u[j].x);
            float2 p1 = __bfloat1622float2(*(__nv_bfloat162*)&u[j].y);
            float2 p2 = __bfloat1622float2(*(__nv_bfloat162*)&u[j].z);
            float2 p3 = __bfloat1622float2(*(__nv_bfloat162*)&u[j].w);
            float v = vv[j];
            acc[0] = fmaf(v, p0.x, acc[0]); acc[1] = fmaf(v, p0.y, acc[1]);
            acc[2] = fmaf(v, p1.x, acc[2]); acc[3] = fmaf(v, p1.y, acc[3]);
            acc[4] = fmaf(v, p2.x, acc[4]); acc[5] = fmaf(v, p2.y, acc[5]);
            acc[6] = fmaf(v, p3.x, acc[6]); acc[7] = fmaf(v, p3.y, acc[7]);
        }
    }
    for (; e < end; e++) {
        int2 ed = g_edge[e];
        float v = __int_as_float(ed.y);
        uint4 u = xb[(size_t)ed.x * D16 + lane];
        float2 p0 = __bfloat1622float2(*(__nv_bfloat162*)&u.x);
        float2 p1 = __bfloat1622float2(*(__nv_bfloat162*)&u.y);
        float2 p2 = __bfloat1622float2(*(__nv_bfloat162*)&u.z);
        float2 p3 = __bfloat1622float2(*(__nv_bfloat162*)&u.w);
        acc[0] = fmaf(v, p0.x, acc[0]); acc[1] = fmaf(v, p0.y, acc[1]);
        acc[2] = fmaf(v, p1.x, acc[2]); acc[3] = fmaf(v, p1.y, acc[3]);
        acc[4] = fmaf(v, p2.x, acc[4]); acc[5] = fmaf(v, p2.y, acc[5]);
        acc[6] = fmaf(v, p3.x, acc[6]); acc[7] = fmaf(v, p3.y, acc[7]);
    }

    int node = nodes[r];
    float4 y0 = y4[(size_t)node * D4 + lane * 2];
    float4 y1 = y4[(size_t)node * D4 + lane * 2 + 1];
    float g[8];
    g[0] = fmaf(0.1f, acc[0], 0.9f * y0.x);
    g[1] = fmaf(0.1f, acc[1], 0.9f * y0.y);
    g[2] = fmaf(0.1f, acc[2], 0.9f * y0.z);
    g[3] = fmaf(0.1f, acc[3], 0.9f * y0.w);
    g[4] = fmaf(0.1f, acc[4], 0.9f * y1.x);
    g[5] = fmaf(0.1f, acc[5], 0.9f * y1.y);
    g[6] = fmaf(0.1f, acc[6], 0.9f * y1.z);
    g[7] = fmaf(0.1f, acc[7], 0.9f * y1.w);

    uint4 uh, ul;
    {
        __nv_bfloat16 h[8], l[8];
#pragma unroll
        for (int q = 0; q < 8; q++) {
            h[q] = __float2bfloat16_rn(g[q]);
            l[q] = __float2bfloat16_rn(g[q] - __bfloat162float(h[q]));
        }
        __nv_bfloat162 a0 = __halves2bfloat162(h[0], h[1]);
        __nv_bfloat162 a1 = __halves2bfloat162(h[2], h[3]);
        __nv_bfloat162 a2 = __halves2bfloat162(h[4], h[5]);
        __nv_bfloat162 a3 = __halves2bfloat162(h[6], h[7]);
        uh.x = *(uint32_t*)&a0; uh.y = *(uint32_t*)&a1;
        uh.z = *(uint32_t*)&a2; uh.w = *(uint32_t*)&a3;
        a0 = __halves2bfloat162(l[0], l[1]);
        a1 = __halves2bfloat162(l[2], l[3]);
        a2 = __halves2bfloat162(l[4], l[5]);
        a3 = __halves2bfloat162(l[6], l[7]);
        ul.x = *(uint32_t*)&a0; ul.y = *(uint32_t*)&a1;
        ul.z = *(uint32_t*)&a2; ul.w = *(uint32_t*)&a3;
    }
    ((uint4*)g_feat_hi)[(size_t)r * D16 + lane] = uh;
    ((uint4*)g_feat_lo)[(size_t)r * D16 + lane] = ul;
    if (g_winner[node] == r + 1) {
        newY4[(size_t)node * D4 + lane * 2]     = make_float4(g[0], g[1], g[2], g[3]);
        newY4[(size_t)node * D4 + lane * 2 + 1] = make_float4(g[4], g[5], g[6], g[7]);
    }
}

// ========== HMMA GEMM m16n8k16 bf16 3-term split, ldmatrix fragments =========
#define AST 24
#define SM_A_HI 0
#define SM_A_LO 3072
#define SM_B_HI 6144
#define SM_B_LO 18432
#define SM_GEMM_TOTAL 30720
#define EP_SUM  0
#define EP_SSQ  2048
#define EP_MEAN 4096
#define EP_RSTD 4352

__device__ __forceinline__ void mma_bf16(float* c, uint32_t a0, uint32_t a1,
                                         uint32_t a2, uint32_t a3,
                                         uint32_t b0, uint32_t b1) {
    asm volatile(
        "mma.sync.aligned.m16n8k16.row.col.f32.bf16.bf16.f32 "
        "{%0,%1,%2,%3}, {%4,%5,%6,%7}, {%8,%9}, {%0,%1,%2,%3};"
        : "+f"(c[0]), "+f"(c[1]), "+f"(c[2]), "+f"(c[3])
        : "r"(a0), "r"(a1), "r"(a2), "r"(a3), "r"(b0), "r"(b1));
}

#define LDMX4(r0, r1, r2, r3, addr) \
    asm volatile("ldmatrix.sync.aligned.m8n8.x4.shared.b16 {%0,%1,%2,%3}, [%4];" \
        : "=r"(r0), "=r"(r1), "=r"(r2), "=r"(r3) : "r"(addr))

__global__ __launch_bounds__(256) void k_gemm_mma(
    const float* __restrict__ bvec, const float* __restrict__ scale,
    const float* __restrict__ offset, float* __restrict__ out,
    int nsamp, int ntotal) {
    __shared__ char sm[SM_GEMM_TOTAL];
    int t = threadIdx.x;
    int warp = t >> 5, lane = t & 31;
    int lq = lane >> 2, lc = lane & 3;
    int wN = warp * 32;
    int rowBase = blockIdx.x * 64;

    float acc[4][4][4];
#pragma unroll
    for (int i = 0; i < 4; i++)
#pragma unroll
        for (int j = 0; j < 4; j++)
#pragma unroll
            for (int q = 0; q < 4; q++) acc[i][j][q] = 0.f;

    int arow = t >> 2, ac4 = t & 3;
    int agrow = rowBase + arow;

    uint32_t sbase = (uint32_t)__cvta_generic_to_shared(sm);
    uint32_t aLaneOff = ((((lane >> 3) & 1) * 8 + (lane & 7)) * AST + (lane >> 4) * 8) * 2;
    uint32_t bLaneOff = (((lane >> 4) * 8 + (lane & 7)) * AST + ((lane >> 3) & 1) * 8) * 2;
    uint32_t aHiAddr = sbase + SM_A_HI + aLaneOff;
    uint32_t aLoAddr = sbase + SM_A_LO + aLaneOff;
    uint32_t bHiAddr = sbase + SM_B_HI + bLaneOff + (uint32_t)(wN * AST * 2);
    uint32_t bLoAddr = sbase + SM_B_LO + bLaneOff + (uint32_t)(wN * AST * 2);

    uint2 pAh, pAl, pBh[4], pBl[4];
    {
        pAh = make_uint2(0u, 0u); pAl = make_uint2(0u, 0u);
        if (agrow < nsamp) {
            pAh = *(const uint2*)&g_feat_hi[(size_t)agrow * D + ac4 * 4];
            pAl = *(const uint2*)&g_feat_lo[(size_t)agrow * D + ac4 * 4];
        }
#pragma unroll
        for (int j = 0; j < 4; j++) {
            int i = t + j * 256;
            int n = i >> 2, c4 = i & 3;
            pBh[j] = *(const uint2*)&g_wt_hi[(size_t)n * D + c4 * 4];
            pBl[j] = *(const uint2*)&g_wt_lo[(size_t)n * D + c4 * 4];
        }
    }

    for (int kc = 0; kc < 16; kc++) {
        *(uint2*)(sm + SM_A_HI + (arow * AST + ac4 * 4) * 2) = pAh;
        *(uint2*)(sm + SM_A_LO + (arow * AST + ac4 * 4) * 2) = pAl;
#pragma unroll
        for (int j = 0; j < 4; j++) {
            int i = t + j * 256;
            int n = i >> 2, c4 = i & 3;
            *(uint2*)(sm + SM_B_HI + (n * AST + c4 * 4) * 2) = pBh[j];
            *(uint2*)(sm + SM_B_LO + (n * AST + c4 * 4) * 2) = pBl[j];
        }
        __syncthreads();

        if (kc < 15) {
            int k0 = (kc + 1) * 16;
            pAh = make_uint2(0u, 0u); pAl = make_uint2(0u, 0u);
            if (agrow < nsamp) {
                pAh = *(const uint2*)&g_feat_hi[(size_t)agrow * D + k0 + ac4 * 4];
                pAl = *(const uint2*)&g_feat_lo[(size_t)agrow * D + k0 + ac4 * 4];
            }
#pragma unroll
            for (int j = 0; j < 4; j++) {
                int i = t + j * 256;
                int n = i >> 2, c4 = i & 3;
                pBh[j] = *(const uint2*)&g_wt_hi[(size_t)n * D + k0 + c4 * 4];
                pBl[j] = *(const uint2*)&g_wt_lo[(size_t)n * D + k0 + c4 * 4];
            }
        }

        uint32_t bh[4][2], bl[4][2];
        LDMX4(bh[0][0], bh[0][1], bh[1][0], bh[1][1], bHiAddr);
        LDMX4(bh[2][0], bh[2][1], bh[3][0], bh[3][1], bHiAddr + 16 * AST * 2);
        LDMX4(bl[0][0], bl[0][1], bl[1][0], bl[1][1], bLoAddr);
        LDMX4(bl[2][0], bl[2][1], bl[3][0], bl[3][1], bLoAddr + 16 * AST * 2);
        {
            uint32_t ah[4][4];
#pragma unroll
            for (int mf = 0; mf < 4; mf++)
                LDMX4(ah[mf][0], ah[mf][1], ah[mf][2], ah[mf][3],
                      aHiAddr + mf * (16 * AST * 2));
#pragma unroll
            for (int mf = 0; mf < 4; mf++)
#pragma unroll
                for (int nf = 0; nf < 4; nf++) {
                    mma_bf16(acc[mf][nf], ah[mf][0], ah[mf][1], ah[mf][2], ah[mf][3],
                             bh[nf][0], bh[nf][1]);
                    mma_bf16(acc[mf][nf], ah[mf][0], ah[mf][1], ah[mf][2], ah[mf][3],
                             bl[nf][0], bl[nf][1]);
                }
        }
        {
            uint32_t al[4][4];
#pragma unroll
            for (int mf = 0; mf < 4; mf++)
                LDMX4(al[mf][0], al[mf][1], al[mf][2], al[mf][3],
                      aLoAddr + mf * (16 * AST * 2));
#pragma unroll
            for (int mf = 0; mf < 4; mf++)
#pragma unroll
                for (int nf = 0; nf < 4; nf++)
                    mma_bf16(acc[mf][nf], al[mf][0], al[mf][1], al[mf][2], al[mf][3],
                             bh[nf][0], bh[nf][1]);
        }
        __syncthreads();
    }

    // ---- epilogue: bias -> ELU -> cross-warp row reduce -> normalize --------
    float bb[4][2], ss[4][2], oo[4][2];
#pragma unroll
    for (int nf = 0; nf < 4; nf++) {
        int col = wN + nf * 8 + lc * 2;
        bb[nf][0] = bvec[col];   bb[nf][1] = bvec[col + 1];
        ss[nf][0] = scale[col];  ss[nf][1] = scale[col + 1];
        oo[nf][0] = offset[col]; oo[nf][1] = offset[col + 1];
    }

    float rs[4][2], rq[4][2];
#pragma unroll
    for (int mf = 0; mf < 4; mf++) { rs[mf][0] = rs[mf][1] = 0.f; rq[mf][0] = rq[mf][1] = 0.f; }
#pragma unroll
    for (int mf = 0; mf < 4; mf++)
#pragma unroll
        for (int nf = 0; nf < 4; nf++) {
            float v0 = acc[mf][nf][0] + bb[nf][0];
            float v1 = acc[mf][nf][1] + bb[nf][1];
            float v2 = acc[mf][nf][2] + bb[nf][0];
            float v3 = acc[mf][nf][3] + bb[nf][1];
            v0 = (v0 > 0.f) ? v0 : expm1f(v0);
            v1 = (v1 > 0.f) ? v1 : expm1f(v1);
            v2 = (v2 > 0.f) ? v2 : expm1f(v2);
            v3 = (v3 > 0.f) ? v3 : expm1f(v3);
            acc[mf][nf][0] = v0; acc[mf][nf][1] = v1;
            acc[mf][nf][2] = v2; acc[mf][nf][3] = v3;
            rs[mf][0] += v0 + v1; rq[mf][0] += v0 * v0 + v1 * v1;
            rs[mf][1] += v2 + v3; rq[mf][1] += v2 * v2 + v3 * v3;
        }
#pragma unroll
    for (int mf = 0; mf < 4; mf++)
#pragma unroll
        for (int h = 0; h < 2; h++) {
            rs[mf][h] += __shfl_xor_sync(0xffffffff, rs[mf][h], 1);
            rs[mf][h] += __shfl_xor_sync(0xffffffff, rs[mf][h], 2);
            rq[mf][h] += __shfl_xor_sync(0xffffffff, rq[mf][h], 1);
            rq[mf][h] += __shfl_xor_sync(0xffffffff, rq[mf][h], 2);
        }
    __syncthreads();
    float* rowsum = (float*)(sm + EP_SUM);
    float* rowssq = (float*)(sm + EP_SSQ);
    if (lc == 0) {
#pragma unroll
        for (int mf = 0; mf < 4; mf++) {
            rowsum[(mf * 16 + lq) * 8 + warp]     = rs[mf][0];
            rowssq[(mf * 16 + lq) * 8 + warp]     = rq[mf][0];
            rowsum[(mf * 16 + 8 + lq) * 8 + warp] = rs[mf][1];
            rowssq[(mf * 16 + 8 + lq) * 8 + warp] = rq[mf][1];
        }
    }
    __syncthreads();
    float* meanA = (float*)(sm + EP_MEAN);
    float* rstdA = (float*)(sm + EP_RSTD);
    if (t < 64) {
        float s = 0.f, q = 0.f;
#pragma unroll
        for (int w = 0; w < 8; w++) { s += rowsum[t * 8 + w]; q += rowssq[t * 8 + w]; }
        float mean = s * (1.f / 256.f);
        float var  = q * (1.f / 256.f) - mean * mean + 1e-9f;
        meanA[t] = mean;
        rstdA[t] = rsqrtf(var);
    }
    __syncthreads();

#pragma unroll
    for (int mf = 0; mf < 4; mf++) {
        int rl = mf * 16 + lq;
        int rh = rl + 8;
        float mL = meanA[rl], rL = rstdA[rl];
        float mH = meanA[rh], rH = rstdA[rh];
        int gl = rowBase + rl, gh = rowBase + rh;
#pragma unroll
        for (int nf = 0; nf < 4; nf++) {
            int col = wN + nf * 8 + lc * 2;
            if (gl < nsamp) {
                float2 p;
                p.x = (acc[mf][nf][0] - mL) * ss[nf][0] * rL + oo[nf][0];
                p.y = (acc[mf][nf][1] - mL) * ss[nf][1] * rL + oo[nf][1];
                *(float2*)(out + (size_t)gl * D + col) = p;
            }
            if (gh < nsamp) {
                float2 p;
                p.x = (acc[mf][nf][2] - mH) * ss[nf][0] * rH + oo[nf][0];
                p.y = (acc[mf][nf][3] - mH) * ss[nf][1] * rH + oo[nf][1];
                *(float2*)(out + (size_t)gh * D + col) = p;
            }
        }
    }

    // reset winner for next invocation (last kernel in the pipeline)
    for (int gi = blockIdx.x * 256 + t; gi < ntotal; gi += gridDim.x * 256)
        g_winner[gi] = 0;
}

// -----------------------------------------------------------------------------
extern "C" void kernel_launch(void* const* d_in, const int* in_sizes, int n_in,
                              void* d_out, int out_size) {
    const float* x        = (const float*)d_in[0];
    const int*   adj_row  = (const int*)d_in[1];
    const int*   adj_col  = (const int*)d_in[2];
    const float* adj_val  = (const float*)d_in[3];
    const int*   nodes    = (const int*)d_in[4];
    const float* y_buf    = (const float*)d_in[5];
    const float* W        = (const float*)d_in[6];
    const float* b        = (const float*)d_in[7];
    const float* scale    = (const float*)d_in[8];
    const float* offset   = (const float*)d_in[9];

    int E      = in_sizes[1];
    int nsamp  = in_sizes[4];
    int nsrc   = in_sizes[0] / D;
    int ntotal = in_sizes[5] / D;

    float* out  = (float*)d_out;
    float* newY = out + (size_t)nsamp * D;

    int G = (nsamp + SCAN_EPB - 1) / SCAN_EPB;
    int spmmB  = (nsamp + 7) / 8;
    int decayB = (ntotal * D4 + 2047) / 2048;
    int convB  = (nsrc * D4 + 1023) / 1024;
    int wB     = (D * D + 255) / 256;
    int histB  = (E + 255) / 256;

    k_prep<<<convB + wB + histB, 256>>>(x, W, adj_row, E, nodes, nsamp, nsrc, convB, wB);
    k_scan<<<G, SCAN_TPB>>>(nsamp, E);
    k_scatter<<<(E + 255) / 256, 256>>>(adj_row, adj_col, adj_val, E, nsamp);
    k_spmm_decay<<<spmmB + decayB, 256>>>(nodes, (const float4*)y_buf, (float4*)newY,
                                          nsamp, ntotal, spmmB, decayB);
    k_gemm_mma<<<(nsamp + 63) / 64, 256>>>(b, scale, offset, out, nsamp, ntotal);
}

// round 12
// speedup vs baseline: 1.4794x; 1.0021x over previous
#include <cuda_runtime.h>
#include <cuda_bf16.h>
#include <math.h>
#include <cstdint>

#define D     256
#define D4    64
#define D16   32                     // uint4 per 256-bf16 row
#define MAX_NSAMP  50000
#define MAX_NSRC   50000
#define MAX_NTOTAL 200000
#define MAX_E      1600000
#define SCAN_TPB   256
#define SCAN_EPB   2048

// ---------------- scratch (static device globals; no allocation) -------------
// Self-cleaning invariants (valid at entry of every kernel_launch call):
//   g_hist == 0 (zeroed by scatter part of k_scatter_conv), g_cursor == 0
//   (zeroed by k_scan), g_winner == 0 (zeroed at end of k_gemm_mma; winner=idx+1)
__device__ __nv_bfloat16 g_xbf[MAX_NSRC * D];
__device__ __nv_bfloat16 g_feat_hi[MAX_NSAMP * D];
__device__ __nv_bfloat16 g_feat_lo[MAX_NSAMP * D];
__device__ __nv_bfloat16 g_wt_hi[D * D];             // W^T hi  [n][k]
__device__ __nv_bfloat16 g_wt_lo[D * D];             // W^T lo
__device__ int   g_hist[MAX_NSAMP];
__device__ int   g_cursor[MAX_NSAMP];
__device__ int   g_rowStart[MAX_NSAMP + 1];
__device__ int   g_winner[MAX_NTOTAL];
__device__ int2  g_edge[MAX_E];

// ================= hist + winner only (feeds the scan immediately) ===========
__global__ void k_hist(const int* __restrict__ row, int E,
                       const int* __restrict__ nodes, int nsamp) {
    int i = blockIdx.x * blockDim.x + threadIdx.x;
    if (i < E) atomicAdd(&g_hist[row[i]], 1);
    if (i < nsamp) atomicMax(&g_winner[nodes[i]], i + 1);   // 0 = empty
}

// ===== single-kernel scan: each block sums its own prefix (G~25, cheap) ======
__global__ __launch_bounds__(SCAN_TPB) void k_scan(int n, int E) {
    __shared__ int sred[SCAN_TPB / 32];
    __shared__ int ws[SCAN_TPB / 32];
    int t = threadIdx.x, lane = t & 31, w = t >> 5;
    int tileStart = blockIdx.x * SCAN_EPB;

    int ps = 0;
    for (int i = t; i < tileStart; i += SCAN_TPB) ps += g_hist[i];
#pragma unroll
    for (int o = 16; o > 0; o >>= 1) ps += __shfl_xor_sync(0xffffffff, ps, o);
    if (lane == 0) sred[w] = ps;

    int base = tileStart + t * 8;
    int v[8], sum = 0;
#pragma unroll
    for (int j = 0; j < 8; j++) {
        int idx = base + j;
        v[j] = (idx < n) ? g_hist[idx] : 0;
        if (idx < n) g_cursor[idx] = 0;
        sum += v[j];
    }
    int x = sum;
#pragma unroll
    for (int o = 1; o < 32; o <<= 1) {
        int y = __shfl_up_sync(0xffffffff, x, o);
        if (lane >= o) x += y;
    }
    if (lane == 31) ws[w] = x;
    __syncthreads();
    if (t == 0) {
        int total = 0;
#pragma unroll
        for (int i = 0; i < SCAN_TPB / 32; i++) total += sred[i];
        int r = total;
#pragma unroll
        for (int i = 0; i < SCAN_TPB / 32; i++) { int q = ws[i]; ws[i] = r; r += q; }
    }
    __syncthreads();
    int run = ws[w] + (x - sum);
#pragma unroll
    for (int j = 0; j < 8; j++) {
        int idx = base + j;
        if (idx < n) g_rowStart[idx] = run;
        run += v[j];
    }
    if (blockIdx.x == 0 && t == 0) g_rowStart[n] = E;
}

// ==== heterogeneous: scatter (+zero hist) || x->bf16 conv || W^T split =======
// Scatter only depends on the scan; x-conv and W-split depend on nothing.
// Fusing them overlaps the scattered-write stream with the big streaming conv.
__global__ void k_scatter_conv(const int* __restrict__ row,
                               const int* __restrict__ col,
                               const float* __restrict__ val, int E, int nsamp,
                               const float* __restrict__ x,
                               const float* __restrict__ W,
                               int nsrc, int scatB, int convB) {
    int b = blockIdx.x;
    int t = threadIdx.x;
    if (b < scatB) {
        int i = b * 256 + t;
        if (i < nsamp) g_hist[i] = 0;           // clean for next call
        if (i < E) {
            int r = row[i];
            int p = g_rowStart[r] + atomicAdd(&g_cursor[r], 1);
            int2 e;
            e.x = col[i];
            e.y = __float_as_int(val[i]);
            g_edge[p] = e;
        }
        return;
    }
    if (b < scatB + convB) {
        long long total = (long long)nsrc * D4;
        long long i0 = (long long)(b - scatB) * 1024 + t;
        const float4* x4 = (const float4*)x;
#pragma unroll
        for (int j = 0; j < 4; j++) {
            long long i = i0 + j * 256;
            if (i < total) {
                float4 v = x4[i];
                __nv_bfloat162 p0 = __floats2bfloat162_rn(v.x, v.y);
                __nv_bfloat162 p1 = __floats2bfloat162_rn(v.z, v.w);
                uint2 u;
                u.x = *(uint32_t*)&p0;
                u.y = *(uint32_t*)&p1;
                ((uint2*)g_xbf)[i] = u;
            }
        }
        return;
    }
    int i = (b - scatB - convB) * 256 + t;
    if (i < D * D) {
        int k = i >> 8, n = i & 255;
        float w = W[k * D + n];
        __nv_bfloat16 hi = __float2bfloat16_rn(w);
        __nv_bfloat16 lo = __float2bfloat16_rn(w - __bfloat162float(hi));
        g_wt_hi[n * D + k] = hi;
        g_wt_lo[n * D + k] = lo;
    }
}

// ====== fused SpMM (warp-per-row) + decay (8x batched, phase-separated) ======
__global__ __launch_bounds__(256) void k_spmm_decay(
    const int* __restrict__ nodes,
    const float4* __restrict__ y4, float4* __restrict__ newY4,
    int nsamp, int ntotal, int spmmB, int decayB) {
    int b = blockIdx.x;
    int t = threadIdx.x;
    int mn = min(spmmB, decayB);
    int nInter = 2 * mn;
    int type, piece;
    if (b < nInter) { type = b & 1; piece = b >> 1; }
    else { type = (spmmB > decayB) ? 0 : 1; piece = mn + (b - nInter); }

    if (type == 1) {
        int total = ntotal * D4;                 // fits int (12.8M)
        int i0 = piece * 2048 + t;
        int ii[8], wv[8];
#pragma unroll
        for (int j = 0; j < 8; j++) {
            ii[j] = i0 + j * 256;
            wv[j] = (ii[j] < total) ? g_winner[ii[j] >> 6] : 1;
        }
        float4 v[8];
#pragma unroll
        for (int j = 0; j < 8; j++)
            if (ii[j] < total && wv[j] == 0) v[j] = y4[ii[j]];
#pragma unroll
        for (int j = 0; j < 8; j++)
            if (ii[j] < total && wv[j] == 0) {
                float4 o;
                o.x = v[j].x * 0.9f; o.y = v[j].y * 0.9f;
                o.z = v[j].z * 0.9f; o.w = v[j].w * 0.9f;
                newY4[ii[j]] = o;
            }
        return;
    }

    // SpMM: one warp per row, lane owns 8 bf16 (one uint4) of the row
    int warp = t >> 5, lane = t & 31;
    int r = piece * 8 + warp;
    if (r >= nsamp) return;
    int e = g_rowStart[r];
    int end = g_rowStart[r + 1];
    const uint4* xb = (const uint4*)g_xbf;
    float acc[8];
#pragma unroll
    for (int q = 0; q < 8; q++) acc[q] = 0.f;

#pragma unroll 1
    for (; e + 8 <= end; e += 8) {
        uint4 u[8];
        float vv[8];
#pragma unroll
        for (int j = 0; j < 8; j++) {
            int2 ed = g_edge[e + j];
            vv[j] = __int_as_float(ed.y);
            u[j] = xb[(size_t)ed.x * D16 + lane];
        }
#pragma unroll
        for (int j = 0; j < 8; j++) {
            float2 p0 = __bfloat1622float2(*(__nv_bfloat162*)&u[j].x);
            float2 p1 = __bfloat1622float2(*(__nv_bfloat162*)&u[j].y);
            float2 p2 = __bfloat1622float2(*(__nv_bfloat162*)&u[j].z);
            float2 p3 = __bfloat1622float2(*(__nv_bfloat162*)&u[j].w);
            float v = vv[j];
            acc[0] = fmaf(v, p0.x, acc[0]); acc[1] = fmaf(v, p0.y, acc[1]);
            acc[2] = fmaf(v, p1.x, acc[2]); acc[3] = fmaf(v, p1.y, acc[3]);
            acc[4] = fmaf(v, p2.x, acc[4]); acc[5] = fmaf(v, p2.y, acc[5]);
            acc[6] = fmaf(v, p3.x, acc[6]); acc[7] = fmaf(v, p3.y, acc[7]);
        }
    }
    for (; e < end; e++) {
        int2 ed = g_edge[e];
        float v = __int_as_float(ed.y);
        uint4 u = xb[(size_t)ed.x * D16 + lane];
        float2 p0 = __bfloat1622float2(*(__nv_bfloat162*)&u.x);
        float2 p1 = __bfloat1622float2(*(__nv_bfloat162*)&u.y);
        float2 p2 = __bfloat1622float2(*(__nv_bfloat162*)&u.z);
        float2 p3 = __bfloat1622float2(*(__nv_bfloat162*)&u.w);
        acc[0] = fmaf(v, p0.x, acc[0]); acc[1] = fmaf(v, p0.y, acc[1]);
        acc[2] = fmaf(v, p1.x, acc[2]); acc[3] = fmaf(v, p1.y, acc[3]);
        acc[4] = fmaf(v, p2.x, acc[4]); acc[5] = fmaf(v, p2.y, acc[5]);
        acc[6] = fmaf(v, p3.x, acc[6]); acc[7] = fmaf(v, p3.y, acc[7]);
    }

    int node = nodes[r];
    float4 y0 = y4[(size_t)node * D4 + lane * 2];
    float4 y1 = y4[(size_t)node * D4 + lane * 2 + 1];
    float g[8];
    g[0] = fmaf(0.1f, acc[0], 0.9f * y0.x);
    g[1] = fmaf(0.1f, acc[1], 0.9f * y0.y);
    g[2] = fmaf(0.1f, acc[2], 0.9f * y0.z);
    g[3] = fmaf(0.1f, acc[3], 0.9f * y0.w);
    g[4] = fmaf(0.1f, acc[4], 0.9f * y1.x);
    g[5] = fmaf(0.1f, acc[5], 0.9f * y1.y);
    g[6] = fmaf(0.1f, acc[6], 0.9f * y1.z);
    g[7] = fmaf(0.1f, acc[7], 0.9f * y1.w);

    uint4 uh, ul;
    {
        __nv_bfloat16 h[8], l[8];
#pragma unroll
        for (int q = 0; q < 8; q++) {
            h[q] = __float2bfloat16_rn(g[q]);
            l[q] = __float2bfloat16_rn(g[q] - __bfloat162float(h[q]));
        }
        __nv_bfloat162 a0 = __halves2bfloat162(h[0], h[1]);
        __nv_bfloat162 a1 = __halves2bfloat162(h[2], h[3]);
        __nv_bfloat162 a2 = __halves2bfloat162(h[4], h[5]);
        __nv_bfloat162 a3 = __halves2bfloat162(h[6], h[7]);
        uh.x = *(uint32_t*)&a0; uh.y = *(uint32_t*)&a1;
        uh.z = *(uint32_t*)&a2; uh.w = *(uint32_t*)&a3;
        a0 = __halves2bfloat162(l[0], l[1]);
        a1 = __halves2bfloat162(l[2], l[3]);
        a2 = __halves2bfloat162(l[4], l[5]);
        a3 = __halves2bfloat162(l[6], l[7]);
        ul.x = *(uint32_t*)&a0; ul.y = *(uint32_t*)&a1;
        ul.z = *(uint32_t*)&a2; ul.w = *(uint32_t*)&a3;
    }
    ((uint4*)g_feat_hi)[(size_t)r * D16 + lane] = uh;
    ((uint4*)g_feat_lo)[(size_t)r * D16 + lane] = ul;
    if (g_winner[node] == r + 1) {
        newY4[(size_t)node * D4 + lane * 2]     = make_float4(g[0], g[1], g[2], g[3]);
        newY4[(size_t)node * D4 + lane * 2 + 1] = make_float4(g[4], g[5], g[6], g[7]);
    }
}

// ========== HMMA GEMM m16n8k16 bf16 3-term split, ldmatrix fragments =========
#define AST 24
#define SM_A_HI 0
#define SM_A_LO 3072
#define SM_B_HI 6144
#define SM_B_LO 18432
#define SM_GEMM_TOTAL 30720
#define EP_SUM  0
#define EP_SSQ  2048
#define EP_MEAN 4096
#define EP_RSTD 4352

__device__ __forceinline__ void mma_bf16(float* c, uint32_t a0, uint32_t a1,
                                         uint32_t a2, uint32_t a3,
                                         uint32_t b0, uint32_t b1) {
    asm volatile(
        "mma.sync.aligned.m16n8k16.row.col.f32.bf16.bf16.f32 "
        "{%0,%1,%2,%3}, {%4,%5,%6,%7}, {%8,%9}, {%0,%1,%2,%3};"
        : "+f"(c[0]), "+f"(c[1]), "+f"(c[2]), "+f"(c[3])
        : "r"(a0), "r"(a1), "r"(a2), "r"(a3), "r"(b0), "r"(b1));
}

#define LDMX4(r0, r1, r2, r3, addr) \
    asm volatile("ldmatrix.sync.aligned.m8n8.x4.shared.b16 {%0,%1,%2,%3}, [%4];" \
        : "=r"(r0), "=r"(r1), "=r"(r2), "=r"(r3) : "r"(addr))

__global__ __launch_bounds__(256) void k_gemm_mma(
    const float* __restrict__ bvec, const float* __restrict__ scale,
    const float* __restrict__ offset, float* __restrict__ out,
    int nsamp, int ntotal) {
    __shared__ char sm[SM_GEMM_TOTAL];
    int t = threadIdx.x;
    int warp = t >> 5, lane = t & 31;
    int lq = lane >> 2, lc = lane & 3;
    int wN = warp * 32;
    int rowBase = blockIdx.x * 64;

    float acc[4][4][4];
#pragma unroll
    for (int i = 0; i < 4; i++)
#pragma unroll
        for (int j = 0; j < 4; j++)
#pragma unroll
            for (int q = 0; q < 4; q++) acc[i][j][q] = 0.f;

    int arow = t >> 2, ac4 = t & 3;
    int agrow = rowBase + arow;

    uint32_t sbase = (uint32_t)__cvta_generic_to_shared(sm);
    uint32_t aLaneOff = ((((lane >> 3) & 1) * 8 + (lane & 7)) * AST + (lane >> 4) * 8) * 2;
    uint32_t bLaneOff = (((lane >> 4) * 8 + (lane & 7)) * AST + ((lane >> 3) & 1) * 8) * 2;
    uint32_t aHiAddr = sbase + SM_A_HI + aLaneOff;
    uint32_t aLoAddr = sbase + SM_A_LO + aLaneOff;
    uint32_t bHiAddr = sbase + SM_B_HI + bLaneOff + (uint32_t)(wN * AST * 2);
    uint32_t bLoAddr = sbase + SM_B_LO + bLaneOff + (uint32_t)(wN * AST * 2);

    uint2 pAh, pAl, pBh[4], pBl[4];
    {
        pAh = make_uint2(0u, 0u); pAl = make_uint2(0u, 0u);
        if (agrow < nsamp) {
            pAh = *(const uint2*)&g_feat_hi[(size_t)agrow * D + ac4 * 4];
            pAl = *(const uint2*)&g_feat_lo[(size_t)agrow * D + ac4 * 4];
        }
#pragma unroll
        for (int j = 0; j < 4; j++) {
            int i = t + j * 256;
            int n = i >> 2, c4 = i & 3;
            pBh[j] = *(const uint2*)&g_wt_hi[(size_t)n * D + c4 * 4];
            pBl[j] = *(const uint2*)&g_wt_lo[(size_t)n * D + c4 * 4];
        }
    }

    for (int kc = 0; kc < 16; kc++) {
        *(uint2*)(sm + SM_A_HI + (arow * AST + ac4 * 4) * 2) = pAh;
        *(uint2*)(sm + SM_A_LO + (arow * AST + ac4 * 4) * 2) = pAl;
#pragma unroll
        for (int j = 0; j < 4; j++) {
            int i = t + j * 256;
            int n = i >> 2, c4 = i & 3;
            *(uint2*)(sm + SM_B_HI + (n * AST + c4 * 4) * 2) = pBh[j];
            *(uint2*)(sm + SM_B_LO + (n * AST + c4 * 4) * 2) = pBl[j];
        }
        __syncthreads();

        if (kc < 15) {
            int k0 = (kc + 1) * 16;
            pAh = make_uint2(0u, 0u); pAl = make_uint2(0u, 0u);
            if (agrow < nsamp) {
                pAh = *(const uint2*)&g_feat_hi[(size_t)agrow * D + k0 + ac4 * 4];
                pAl = *(const uint2*)&g_feat_lo[(size_t)agrow * D + k0 + ac4 * 4];
            }
#pragma unroll
            for (int j = 0; j < 4; j++) {
                int i = t + j * 256;
                int n = i >> 2, c4 = i & 3;
                pBh[j] = *(const uint2*)&g_wt_hi[(size_t)n * D + k0 + c4 * 4];
                pBl[j] = *(const uint2*)&g_wt_lo[(size_t)n * D + k0 + c4 * 4];
            }
        }

        uint32_t bh[4][2], bl[4][2];
        LDMX4(bh[0][0], bh[0][1], bh[1][0], bh[1][1], bHiAddr);
        LDMX4(bh[2][0], bh[2][1], bh[3][0], bh[3][1], bHiAddr + 16 * AST * 2);
        LDMX4(bl[0][0], bl[0][1], bl[1][0], bl[1][1], bLoAddr);
        LDMX4(bl[2][0], bl[2][1], bl[3][0], bl[3][1], bLoAddr + 16 * AST * 2);
        {
            uint32_t ah[4][4];
#pragma unroll
            for (int mf = 0; mf < 4; mf++)
                LDMX4(ah[mf][0], ah[mf][1], ah[mf][2], ah[mf][3],
                      aHiAddr + mf * (16 * AST * 2));
#pragma unroll
            for (int mf = 0; mf < 4; mf++)
#pragma unroll
                for (int nf = 0; nf < 4; nf++) {
                    mma_bf16(acc[mf][nf], ah[mf][0], ah[mf][1], ah[mf][2], ah[mf][3],
                             bh[nf][0], bh[nf][1]);
                    mma_bf16(acc[mf][nf], ah[mf][0], ah[mf][1], ah[mf][2], ah[mf][3],
                             bl[nf][0], bl[nf][1]);
                }
        }
        {
            uint32_t al[4][4];
#pragma unroll
            for (int mf = 0; mf < 4; mf++)
                LDMX4(al[mf][0], al[mf][1], al[mf][2], al[mf][3],
                      aLoAddr + mf * (16 * AST * 2));
#pragma unroll
            for (int mf = 0; mf < 4; mf++)
#pragma unroll
                for (int nf = 0; nf < 4; nf++)
                    mma_bf16(acc[mf][nf], al[mf][0], al[mf][1], al[mf][2], al[mf][3],
                             bh[nf][0], bh[nf][1]);
        }
        __syncthreads();
    }

    // ---- epilogue: bias -> ELU -> cross-warp row reduce -> normalize --------
    float bb[4][2], ss[4][2], oo[4][2];
#pragma unroll
    for (int nf = 0; nf < 4; nf++) {
        int col = wN + nf * 8 + lc * 2;
        bb[nf][0] = bvec[col];   bb[nf][1] = bvec[col + 1];
        ss[nf][0] = scale[col];  ss[nf][1] = scale[col + 1];
        oo[nf][0] = offset[col]; oo[nf][1] = offset[col + 1];
    }

    float rs[4][2], rq[4][2];
#pragma unroll
    for (int mf = 0; mf < 4; mf++) { rs[mf][0] = rs[mf][1] = 0.f; rq[mf][0] = rq[mf][1] = 0.f; }
#pragma unroll
    for (int mf = 0; mf < 4; mf++)
#pragma unroll
        for (int nf = 0; nf < 4; nf++) {
            float v0 = acc[mf][nf][0] + bb[nf][0];
            float v1 = acc[mf][nf][1] + bb[nf][1];
            float v2 = acc[mf][nf][2] + bb[nf][0];
            float v3 = acc[mf][nf][3] + bb[nf][1];
            v0 = (v0 > 0.f) ? v0 : expm1f(v0);
            v1 = (v1 > 0.f) ? v1 : expm1f(v1);
            v2 = (v2 > 0.f) ? v2 : expm1f(v2);
            v3 = (v3 > 0.f) ? v3 : expm1f(v3);
            acc[mf][nf][0] = v0; acc[mf][nf][1] = v1;
            acc[mf][nf][2] = v2; acc[mf][nf][3] = v3;
            rs[mf][0] += v0 + v1; rq[mf][0] += v0 * v0 + v1 * v1;
            rs[mf][1] += v2 + v3; rq[mf][1] += v2 * v2 + v3 * v3;
        }
#pragma unroll
    for (int mf = 0; mf < 4; mf++)
#pragma unroll
        for (int h = 0; h < 2; h++) {
            rs[mf][h] += __shfl_xor_sync(0xffffffff, rs[mf][h], 1);
            rs[mf][h] += __shfl_xor_sync(0xffffffff, rs[mf][h], 2);
            rq[mf][h] += __shfl_xor_sync(0xffffffff, rq[mf][h], 1);
            rq[mf][h] += __shfl_xor_sync(0xffffffff, rq[mf][h], 2);
        }
    __syncthreads();
    float* rowsum = (float*)(sm + EP_SUM);
    float* rowssq = (float*)(sm + EP_SSQ);
    if (lc == 0) {
#pragma unroll
        for (int mf = 0; mf < 4; mf++) {
            rowsum[(mf * 16 + lq) * 8 + warp]     = rs[mf][0];
            rowssq[(mf * 16 + lq) * 8 + warp]     = rq[mf][0];
            rowsum[(mf * 16 + 8 + lq) * 8 + warp] = rs[mf][1];
            rowssq[(mf * 16 + 8 + lq) * 8 + warp] = rq[mf][1];
        }
    }
    __syncthreads();
    float* meanA = (float*)(sm + EP_MEAN);
    float* rstdA = (float*)(sm + EP_RSTD);
    if (t < 64) {
        float s = 0.f, q = 0.f;
#pragma unroll
        for (int w = 0; w < 8; w++) { s += rowsum[t * 8 + w]; q += rowssq[t * 8 + w]; }
        float mean = s * (1.f / 256.f);
        float var  = q * (1.f / 256.f) - mean * mean + 1e-9f;
        meanA[t] = mean;
        rstdA[t] = rsqrtf(var);
    }
    __syncthreads();

#pragma unroll
    for (int mf = 0; mf < 4; mf++) {
        int rl = mf * 16 + lq;
        int rh = rl + 8;
        float mL = meanA[rl], rL = rstdA[rl];
        float mH = meanA[rh], rH = rstdA[rh];
        int gl = rowBase + rl, gh = rowBase + rh;
#pragma unroll
        for (int nf = 0; nf < 4; nf++) {
            int col = wN + nf * 8 + lc * 2;
            if (gl < nsamp) {
                float2 p;
                p.x = (acc[mf][nf][0] - mL) * ss[nf][0] * rL + oo[nf][0];
                p.y = (acc[mf][nf][1] - mL) * ss[nf][1] * rL + oo[nf][1];
                *(float2*)(out + (size_t)gl * D + col) = p;
            }
            if (gh < nsamp) {
                float2 p;
                p.x = (acc[mf][nf][2] - mH) * ss[nf][0] * rH + oo[nf][0];
                p.y = (acc[mf][nf][3] - mH) * ss[nf][1] * rH + oo[nf][1];
                *(float2*)(out + (size_t)gh * D + col) = p;
            }
        }
    }

    // reset winner for next invocation (last kernel in the pipeline)
    for (int gi = blockIdx.x * 256 + t; gi < ntotal; gi += gridDim.x * 256)
        g_winner[gi] = 0;
}

// -----------------------------------------------------------------------------
extern "C" void kernel_launch(void* const* d_in, const int* in_sizes, int n_in,
                              void* d_out, int out_size) {
    const float* x        = (const float*)d_in[0];
    const int*   adj_row  = (const int*)d_in[1];
    const int*   adj_col  = (const int*)d_in[2];
    const float* adj_val  = (const float*)d_in[3];
    const int*   nodes    = (const int*)d_in[4];
    const float* y_buf    = (const float*)d_in[5];
    const float* W        = (const float*)d_in[6];
    const float* b        = (const float*)d_in[7];
    const float* scale    = (const float*)d_in[8];
    const float* offset   = (const float*)d_in[9];

    int E      = in_sizes[1];
    int nsamp  = in_sizes[4];
    int nsrc   = in_sizes[0] / D;
    int ntotal = in_sizes[5] / D;

    float* out  = (float*)d_out;
    float* newY = out + (size_t)nsamp * D;

    int G = (nsamp + SCAN_EPB - 1) / SCAN_EPB;
    int spmmB  = (nsamp + 7) / 8;
    int decayB = (ntotal * D4 + 2047) / 2048;
    int scatB  = (E + 255) / 256;
    int convB  = (nsrc * D4 + 1023) / 1024;
    int wB     = (D * D + 255) / 256;

    k_hist<<<(E + 255) / 256, 256>>>(adj_row, E, nodes, nsamp);
    k_scan<<<G, SCAN_TPB>>>(nsamp, E);
    k_scatter_conv<<<scatB + convB + wB, 256>>>(adj_row, adj_col, adj_val, E, nsamp,
                                                x, W, nsrc, scatB, convB);
    k_spmm_decay<<<spmmB + decayB, 256>>>(nodes, (const float4*)y_buf, (float4*)newY,
                                          nsamp, ntotal, spmmB, decayB);
    k_gemm_mma<<<(nsamp + 63) / 64, 256>>>(b, scale, offset, out, nsamp, ntotal);
}

// round 13
// speedup vs baseline: 1.4950x; 1.0105x over previous
#include <cuda_runtime.h>
#include <cuda_bf16.h>
#include <math.h>
#include <cstdint>

#define D     256
#define D4    64
#define D16   32                     // uint4 per 256-bf16 row
#define MAX_NSAMP  50000
#define MAX_NSRC   50000
#define MAX_NTOTAL 200000
#define MAX_E      1600000
#define SCAN_TPB   256
#define SCAN_EPB   2048

// ---------------- scratch (static device globals; no allocation) -------------
// Self-cleaning invariants (valid at entry of every kernel_launch call):
//   g_hist == 0 (zeroed by scatter part of k_scatter_conv), g_cursor == 0
//   (zeroed by k_scan), g_winner == 0 (zeroed at end of k_gemm_mma; winner=idx+1)
__device__ __nv_bfloat16 g_xbf[MAX_NSRC * D];
__device__ __nv_bfloat16 g_feat_hi[MAX_NSAMP * D];
__device__ __nv_bfloat16 g_feat_lo[MAX_NSAMP * D];
__device__ __nv_bfloat16 g_wt_hi[D * D];             // W^T hi  [n][k]
__device__ __nv_bfloat16 g_wt_lo[D * D];             // W^T lo
__device__ int   g_hist[MAX_NSAMP];
__device__ int   g_cursor[MAX_NSAMP];
__device__ int   g_rowStart[MAX_NSAMP + 1];
__device__ int   g_winner[MAX_NTOTAL];
__device__ int2  g_edge[MAX_E];

// ================= hist + winner only (feeds the scan immediately) ===========
__global__ void k_hist(const int* __restrict__ row, int E,
                       const int* __restrict__ nodes, int nsamp) {
    int i = blockIdx.x * blockDim.x + threadIdx.x;
    if (i < E) atomicAdd(&g_hist[row[i]], 1);
    if (i < nsamp) atomicMax(&g_winner[nodes[i]], i + 1);   // 0 = empty
}

// ===== single-kernel scan: each block sums its own prefix (G~25, cheap) ======
__global__ __launch_bounds__(SCAN_TPB) void k_scan(int n, int E) {
    __shared__ int sred[SCAN_TPB / 32];
    __shared__ int ws[SCAN_TPB / 32];
    int t = threadIdx.x, lane = t & 31, w = t >> 5;
    int tileStart = blockIdx.x * SCAN_EPB;

    int ps = 0;
    for (int i = t; i < tileStart; i += SCAN_TPB) ps += g_hist[i];
#pragma unroll
    for (int o = 16; o > 0; o >>= 1) ps += __shfl_xor_sync(0xffffffff, ps, o);
    if (lane == 0) sred[w] = ps;

    int base = tileStart + t * 8;
    int v[8], sum = 0;
#pragma unroll
    for (int j = 0; j < 8; j++) {
        int idx = base + j;
        v[j] = (idx < n) ? g_hist[idx] : 0;
        if (idx < n) g_cursor[idx] = 0;
        sum += v[j];
    }
    int x = sum;
#pragma unroll
    for (int o = 1; o < 32; o <<= 1) {
        int y = __shfl_up_sync(0xffffffff, x, o);
        if (lane >= o) x += y;
    }
    if (lane == 31) ws[w] = x;
    __syncthreads();
    if (t == 0) {
        int total = 0;
#pragma unroll
        for (int i = 0; i < SCAN_TPB / 32; i++) total += sred[i];
        int r = total;
#pragma unroll
        for (int i = 0; i < SCAN_TPB / 32; i++) { int q = ws[i]; ws[i] = r; r += q; }
    }
    __syncthreads();
    int run = ws[w] + (x - sum);
#pragma unroll
    for (int j = 0; j < 8; j++) {
        int idx = base + j;
        if (idx < n) g_rowStart[idx] = run;
        run += v[j];
    }
    if (blockIdx.x == 0 && t == 0) g_rowStart[n] = E;
}

// ==== heterogeneous: scatter (+zero hist) || x->bf16 conv || W^T split =======
__global__ void k_scatter_conv(const int* __restrict__ row,
                               const int* __restrict__ col,
                               const float* __restrict__ val, int E, int nsamp,
                               const float* __restrict__ x,
                               const float* __restrict__ W,
                               int nsrc, int scatB, int convB) {
    int b = blockIdx.x;
    int t = threadIdx.x;
    if (b < scatB) {
        int i = b * 256 + t;
        if (i < nsamp) g_hist[i] = 0;           // clean for next call
        if (i < E) {
            int r = row[i];
            int p = g_rowStart[r] + atomicAdd(&g_cursor[r], 1);
            int2 e;
            e.x = col[i];
            e.y = __float_as_int(val[i]);
            g_edge[p] = e;
        }
        return;
    }
    if (b < scatB + convB) {
        long long total = (long long)nsrc * D4;
        long long i0 = (long long)(b - scatB) * 1024 + t;
        const float4* x4 = (const float4*)x;
#pragma unroll
        for (int j = 0; j < 4; j++) {
            long long i = i0 + j * 256;
            if (i < total) {
                float4 v = x4[i];
                __nv_bfloat162 p0 = __floats2bfloat162_rn(v.x, v.y);
                __nv_bfloat162 p1 = __floats2bfloat162_rn(v.z, v.w);
                uint2 u;
                u.x = *(uint32_t*)&p0;
                u.y = *(uint32_t*)&p1;
                ((uint2*)g_xbf)[i] = u;
            }
        }
        return;
    }
    int i = (b - scatB - convB) * 256 + t;
    if (i < D * D) {
        int k = i >> 8, n = i & 255;
        float w = W[k * D + n];
        __nv_bfloat16 hi = __float2bfloat16_rn(w);
        __nv_bfloat16 lo = __float2bfloat16_rn(w - __bfloat162float(hi));
        g_wt_hi[n * D + k] = hi;
        g_wt_lo[n * D + k] = lo;
    }
}

// ====== fused SpMM (warp-per-row) + decay (8x batched, phase-separated) ======
__global__ __launch_bounds__(256) void k_spmm_decay(
    const int* __restrict__ nodes,
    const float4* __restrict__ y4, float4* __restrict__ newY4,
    int nsamp, int ntotal, int spmmB, int decayB) {
    int b = blockIdx.x;
    int t = threadIdx.x;
    int mn = min(spmmB, decayB);
    int nInter = 2 * mn;
    int type, piece;
    if (b < nInter) { type = b & 1; piece = b >> 1; }
    else { type = (spmmB > decayB) ? 0 : 1; piece = mn + (b - nInter); }

    if (type == 1) {
        int total = ntotal * D4;                 // fits int (12.8M)
        int i0 = piece * 2048 + t;
        int ii[8], wv[8];
#pragma unroll
        for (int j = 0; j < 8; j++) {
            ii[j] = i0 + j * 256;
            wv[j] = (ii[j] < total) ? g_winner[ii[j] >> 6] : 1;
        }
        float4 v[8];
#pragma unroll
        for (int j = 0; j < 8; j++)
            if (ii[j] < total && wv[j] == 0) v[j] = y4[ii[j]];
#pragma unroll
        for (int j = 0; j < 8; j++)
            if (ii[j] < total && wv[j] == 0) {
                float4 o;
                o.x = v[j].x * 0.9f; o.y = v[j].y * 0.9f;
                o.z = v[j].z * 0.9f; o.w = v[j].w * 0.9f;
                newY4[ii[j]] = o;
            }
        return;
    }

    // SpMM: one warp per row, lane owns 8 bf16 (one uint4) of the row
    int warp = t >> 5, lane = t & 31;
    int r = piece * 8 + warp;
    if (r >= nsamp) return;
    int e = g_rowStart[r];
    int end = g_rowStart[r + 1];
    const uint4* xb = (const uint4*)g_xbf;
    float acc[8];
#pragma unroll
    for (int q = 0; q < 8; q++) acc[q] = 0.f;

#pragma unroll 1
    for (; e + 8 <= end; e += 8) {
        uint4 u[8];
        float vv[8];
#pragma unroll
        for (int j = 0; j < 8; j++) {
            int2 ed = g_edge[e + j];
            vv[j] = __int_as_float(ed.y);
            u[j] = xb[(size_t)ed.x * D16 + lane];
        }
#pragma unroll
        for (int j = 0; j < 8; j++) {
            float2 p0 = __bfloat1622float2(*(__nv_bfloat162*)&u[j].x);
            float2 p1 = __bfloat1622float2(*(__nv_bfloat162*)&u[j].y);
            float2 p2 = __bfloat1622float2(*(__nv_bfloat162*)&u[j].z);
            float2 p3 = __bfloat1622float2(*(__nv_bfloat162*)&u[j].w);
            float v = vv[j];
            acc[0] = fmaf(v, p0.x, acc[0]); acc[1] = fmaf(v, p0.y, acc[1]);
            acc[2] = fmaf(v, p1.x, acc[2]); acc[3] = fmaf(v, p1.y, acc[3]);
            acc[4] = fmaf(v, p2.x, acc[4]); acc[5] = fmaf(v, p2.y, acc[5]);
            acc[6] = fmaf(v, p3.x, acc[6]); acc[7] = fmaf(v, p3.y, acc[7]);
        }
    }
    for (; e < end; e++) {
        int2 ed = g_edge[e];
        float v = __int_as_float(ed.y);
        uint4 u = xb[(size_t)ed.x * D16 + lane];
        float2 p0 = __bfloat1622float2(*(__nv_bfloat162*)&u.x);
        float2 p1 = __bfloat1622float2(*(__nv_bfloat162*)&u.y);
        float2 p2 = __bfloat1622float2(*(__nv_bfloat162*)&u.z);
        float2 p3 = __bfloat1622float2(*(__nv_bfloat162*)&u.w);
        acc[0] = fmaf(v, p0.x, acc[0]); acc[1] = fmaf(v, p0.y, acc[1]);
        acc[2] = fmaf(v, p1.x, acc[2]); acc[3] = fmaf(v, p1.y, acc[3]);
        acc[4] = fmaf(v, p2.x, acc[4]); acc[5] = fmaf(v, p2.y, acc[5]);
        acc[6] = fmaf(v, p3.x, acc[6]); acc[7] = fmaf(v, p3.y, acc[7]);
    }

    int node = nodes[r];
    float4 y0 = y4[(size_t)node * D4 + lane * 2];
    float4 y1 = y4[(size_t)node * D4 + lane * 2 + 1];
    float g[8];
    g[0] = fmaf(0.1f, acc[0], 0.9f * y0.x);
    g[1] = fmaf(0.1f, acc[1], 0.9f * y0.y);
    g[2] = fmaf(0.1f, acc[2], 0.9f * y0.z);
    g[3] = fmaf(0.1f, acc[3], 0.9f * y0.w);
    g[4] = fmaf(0.1f, acc[4], 0.9f * y1.x);
    g[5] = fmaf(0.1f, acc[5], 0.9f * y1.y);
    g[6] = fmaf(0.1f, acc[6], 0.9f * y1.z);
    g[7] = fmaf(0.1f, acc[7], 0.9f * y1.w);

    uint4 uh, ul;
    {
        __nv_bfloat16 h[8], l[8];
#pragma unroll
        for (int q = 0; q < 8; q++) {
            h[q] = __float2bfloat16_rn(g[q]);
            l[q] = __float2bfloat16_rn(g[q] - __bfloat162float(h[q]));
        }
        __nv_bfloat162 a0 = __halves2bfloat162(h[0], h[1]);
        __nv_bfloat162 a1 = __halves2bfloat162(h[2], h[3]);
        __nv_bfloat162 a2 = __halves2bfloat162(h[4], h[5]);
        __nv_bfloat162 a3 = __halves2bfloat162(h[6], h[7]);
        uh.x = *(uint32_t*)&a0; uh.y = *(uint32_t*)&a1;
        uh.z = *(uint32_t*)&a2; uh.w = *(uint32_t*)&a3;
        a0 = __halves2bfloat162(l[0], l[1]);
        a1 = __halves2bfloat162(l[2], l[3]);
        a2 = __halves2bfloat162(l[4], l[5]);
        a3 = __halves2bfloat162(l[6], l[7]);
        ul.x = *(uint32_t*)&a0; ul.y = *(uint32_t*)&a1;
        ul.z = *(uint32_t*)&a2; ul.w = *(uint32_t*)&a3;
    }
    ((uint4*)g_feat_hi)[(size_t)r * D16 + lane] = uh;
    ((uint4*)g_feat_lo)[(size_t)r * D16 + lane] = ul;
    if (g_winner[node] == r + 1) {
        newY4[(size_t)node * D4 + lane * 2]     = make_float4(g[0], g[1], g[2], g[3]);
        newY4[(size_t)node * D4 + lane * 2 + 1] = make_float4(g[4], g[5], g[6], g[7]);
    }
}

// == HMMA GEMM m16n8k16 bf16 3-term split, ldmatrix + 2-stage double buffer ===
// Register file caps residency at ~2 CTAs/SM, so doubling smem to 60KB costs
// no occupancy; single __syncthreads per k-chunk (16 barriers instead of 32).
#define AST 24
#define SM_A_HI 0
#define SM_A_LO 3072
#define SM_B_HI 6144
#define SM_B_LO 18432
#define STG     30720
#define SM_GEMM_TOTAL (2 * STG)
#define EP_SUM  0
#define EP_SSQ  2048
#define EP_MEAN 4096
#define EP_RSTD 4352

__device__ __forceinline__ void mma_bf16(float* c, uint32_t a0, uint32_t a1,
                                         uint32_t a2, uint32_t a3,
                                         uint32_t b0, uint32_t b1) {
    asm volatile(
        "mma.sync.aligned.m16n8k16.row.col.f32.bf16.bf16.f32 "
        "{%0,%1,%2,%3}, {%4,%5,%6,%7}, {%8,%9}, {%0,%1,%2,%3};"
        : "+f"(c[0]), "+f"(c[1]), "+f"(c[2]), "+f"(c[3])
        : "r"(a0), "r"(a1), "r"(a2), "r"(a3), "r"(b0), "r"(b1));
}

#define LDMX4(r0, r1, r2, r3, addr) \
    asm volatile("ldmatrix.sync.aligned.m8n8.x4.shared.b16 {%0,%1,%2,%3}, [%4];" \
        : "=r"(r0), "=r"(r1), "=r"(r2), "=r"(r3) : "r"(addr))

__global__ __launch_bounds__(256) void k_gemm_mma(
    const float* __restrict__ bvec, const float* __restrict__ scale,
    const float* __restrict__ offset, float* __restrict__ out,
    int nsamp, int ntotal) {
    extern __shared__ char sm[];
    int t = threadIdx.x;
    int warp = t >> 5, lane = t & 31;
    int lq = lane >> 2, lc = lane & 3;
    int wN = warp * 32;
    int rowBase = blockIdx.x * 64;

    float acc[4][4][4];
#pragma unroll
    for (int i = 0; i < 4; i++)
#pragma unroll
        for (int j = 0; j < 4; j++)
#pragma unroll
            for (int q = 0; q < 4; q++) acc[i][j][q] = 0.f;

    int arow = t >> 2, ac4 = t & 3;
    int agrow = rowBase + arow;

    uint32_t sbase = (uint32_t)__cvta_generic_to_shared(sm);
    uint32_t aLaneOff = ((((lane >> 3) & 1) * 8 + (lane & 7)) * AST + (lane >> 4) * 8) * 2;
    uint32_t bLaneOff = (((lane >> 4) * 8 + (lane & 7)) * AST + ((lane >> 3) & 1) * 8) * 2;
    uint32_t aHiAddr = sbase + SM_A_HI + aLaneOff;
    uint32_t aLoAddr = sbase + SM_A_LO + aLaneOff;
    uint32_t bHiAddr = sbase + SM_B_HI + bLaneOff + (uint32_t)(wN * AST * 2);
    uint32_t bLoAddr = sbase + SM_B_LO + bLaneOff + (uint32_t)(wN * AST * 2);

    uint2 pAh, pAl, pBh[4], pBl[4];
    {
        pAh = make_uint2(0u, 0u); pAl = make_uint2(0u, 0u);
        if (agrow < nsamp) {
            pAh = *(const uint2*)&g_feat_hi[(size_t)agrow * D + ac4 * 4];
            pAl = *(const uint2*)&g_feat_lo[(size_t)agrow * D + ac4 * 4];
        }
#pragma unroll
        for (int j = 0; j < 4; j++) {
            int i = t + j * 256;
            int n = i >> 2, c4 = i & 3;
            pBh[j] = *(const uint2*)&g_wt_hi[(size_t)n * D + c4 * 4];
            pBl[j] = *(const uint2*)&g_wt_lo[(size_t)n * D + c4 * 4];
        }
    }

    for (int kc = 0; kc < 16; kc++) {
        uint32_t cur = (uint32_t)(kc & 1) * STG;
        // commit prefetched tile into the CURRENT stage (other warps may still
        // be doing MMA on the OTHER stage - no conflict, one sync suffices)
        *(uint2*)(sm + cur + SM_A_HI + (arow * AST + ac4 * 4) * 2) = pAh;
        *(uint2*)(sm + cur + SM_A_LO + (arow * AST + ac4 * 4) * 2) = pAl;
#pragma unroll
        for (int j = 0; j < 4; j++) {
            int i = t + j * 256;
            int n = i >> 2, c4 = i & 3;
            *(uint2*)(sm + cur + SM_B_HI + (n * AST + c4 * 4) * 2) = pBh[j];
            *(uint2*)(sm + cur + SM_B_LO + (n * AST + c4 * 4) * 2) = pBl[j];
        }
        __syncthreads();

        if (kc < 15) {
            int k0 = (kc + 1) * 16;
            pAh = make_uint2(0u, 0u); pAl = make_uint2(0u, 0u);
            if (agrow < nsamp) {
                pAh = *(const uint2*)&g_feat_hi[(size_t)agrow * D + k0 + ac4 * 4];
                pAl = *(const uint2*)&g_feat_lo[(size_t)agrow * D + k0 + ac4 * 4];
            }
#pragma unroll
            for (int j = 0; j < 4; j++) {
                int i = t + j * 256;
                int n = i >> 2, c4 = i & 3;
                pBh[j] = *(const uint2*)&g_wt_hi[(size_t)n * D + k0 + c4 * 4];
                pBl[j] = *(const uint2*)&g_wt_lo[(size_t)n * D + k0 + c4 * 4];
            }
        }

        uint32_t bh[4][2], bl[4][2];
        LDMX4(bh[0][0], bh[0][1], bh[1][0], bh[1][1], bHiAddr + cur);
        LDMX4(bh[2][0], bh[2][1], bh[3][0], bh[3][1], bHiAddr + cur + 16 * AST * 2);
        LDMX4(bl[0][0], bl[0][1], bl[1][0], bl[1][1], bLoAddr + cur);
        LDMX4(bl[2][0], bl[2][1], bl[3][0], bl[3][1], bLoAddr + cur + 16 * AST * 2);
        {
            uint32_t ah[4][4];
#pragma unroll
            for (int mf = 0; mf < 4; mf++)
                LDMX4(ah[mf][0], ah[mf][1], ah[mf][2], ah[mf][3],
                      aHiAddr + cur + mf * (16 * AST * 2));
#pragma unroll
            for (int mf = 0; mf < 4; mf++)
#pragma unroll
                for (int nf = 0; nf < 4; nf++) {
                    mma_bf16(acc[mf][nf], ah[mf][0], ah[mf][1], ah[mf][2], ah[mf][3],
                             bh[nf][0], bh[nf][1]);
                    mma_bf16(acc[mf][nf], ah[mf][0], ah[mf][1], ah[mf][2], ah[mf][3],
                             bl[nf][0], bl[nf][1]);
                }
        }
        {
            uint32_t al[4][4];
#pragma unroll
            for (int mf = 0; mf < 4; mf++)
                LDMX4(al[mf][0], al[mf][1], al[mf][2], al[mf][3],
                      aLoAddr + cur + mf * (16 * AST * 2));
#pragma unroll
            for (int mf = 0; mf < 4; mf++)
#pragma unroll
                for (int nf = 0; nf < 4; nf++)
                    mma_bf16(acc[mf][nf], al[mf][0], al[mf][1], al[mf][2], al[mf][3],
                             bh[nf][0], bh[nf][1]);
        }
        // no trailing sync: next iteration writes the OTHER stage
    }

    // ---- epilogue: bias -> ELU -> cross-warp row reduce -> normalize --------
    float bb[4][2], ss[4][2], oo[4][2];
#pragma unroll
    for (int nf = 0; nf < 4; nf++) {
        int col = wN + nf * 8 + lc * 2;
        bb[nf][0] = bvec[col];   bb[nf][1] = bvec[col + 1];
        ss[nf][0] = scale[col];  ss[nf][1] = scale[col + 1];
        oo[nf][0] = offset[col]; oo[nf][1] = offset[col + 1];
    }

    float rs[4][2], rq[4][2];
#pragma unroll
    for (int mf = 0; mf < 4; mf++) { rs[mf][0] = rs[mf][1] = 0.f; rq[mf][0] = rq[mf][1] = 0.f; }
#pragma unroll
    for (int mf = 0; mf < 4; mf++)
#pragma unroll
        for (int nf = 0; nf < 4; nf++) {
            float v0 = acc[mf][nf][0] + bb[nf][0];
            float v1 = acc[mf][nf][1] + bb[nf][1];
            float v2 = acc[mf][nf][2] + bb[nf][0];
            float v3 = acc[mf][nf][3] + bb[nf][1];
            v0 = (v0 > 0.f) ? v0 : expm1f(v0);
            v1 = (v1 > 0.f) ? v1 : expm1f(v1);
            v2 = (v2 > 0.f) ? v2 : expm1f(v2);
            v3 = (v3 > 0.f) ? v3 : expm1f(v3);
            acc[mf][nf][0] = v0; acc[mf][nf][1] = v1;
            acc[mf][nf][2] = v2; acc[mf][nf][3] = v3;
            rs[mf][0] += v0 + v1; rq[mf][0] += v0 * v0 + v1 * v1;
            rs[mf][1] += v2 + v3; rq[mf][1] += v2 * v2 + v3 * v3;
        }
#pragma unroll
    for (int mf = 0; mf < 4; mf++)
#pragma unroll
        for (int h = 0; h < 2; h++) {
            rs[mf][h] += __shfl_xor_sync(0xffffffff, rs[mf][h], 1);
            rs[mf][h] += __shfl_xor_sync(0xffffffff, rs[mf][h], 2);
            rq[mf][h] += __shfl_xor_sync(0xffffffff, rq[mf][h], 1);
            rq[mf][h] += __shfl_xor_sync(0xffffffff, rq[mf][h], 2);
        }
    __syncthreads();                 // all MMA smem reads done -> safe to alias
    float* rowsum = (float*)(sm + EP_SUM);
    float* rowssq = (float*)(sm + EP_SSQ);
    if (lc == 0) {
#pragma unroll
        for (int mf = 0; mf < 4; mf++) {
            rowsum[(mf * 16 + lq) * 8 + warp]     = rs[mf][0];
            rowssq[(mf * 16 + lq) * 8 + warp]     = rq[mf][0];
            rowsum[(mf * 16 + 8 + lq) * 8 + warp] = rs[mf][1];
            rowssq[(mf * 16 + 8 + lq) * 8 + warp] = rq[mf][1];
        }
    }
    __syncthreads();
    float* meanA = (float*)(sm + EP_MEAN);
    float* rstdA = (float*)(sm + EP_RSTD);
    if (t < 64) {
        float s = 0.f, q = 0.f;
#pragma unroll
        for (int w = 0; w < 8; w++) { s += rowsum[t * 8 + w]; q += rowssq[t * 8 + w]; }
        float mean = s * (1.f / 256.f);
        float var  = q * (1.f / 256.f) - mean * mean + 1e-9f;
        meanA[t] = mean;
        rstdA[t] = rsqrtf(var);
    }
    __syncthreads();

#pragma unroll
    for (int mf = 0; mf < 4; mf++) {
        int rl = mf * 16 + lq;
        int rh = rl + 8;
        float mL = meanA[rl], rL = rstdA[rl];
        float mH = meanA[rh], rH = rstdA[rh];
        int gl = rowBase + rl, gh = rowBase + rh;
#pragma unroll
        for (int nf = 0; nf < 4; nf++) {
            int col = wN + nf * 8 + lc * 2;
            if (gl < nsamp) {
                float2 p;
                p.x = (acc[mf][nf][0] - mL) * ss[nf][0] * rL + oo[nf][0];
                p.y = (acc[mf][nf][1] - mL) * ss[nf][1] * rL + oo[nf][1];
                *(float2*)(out + (size_t)gl * D + col) = p;
            }
            if (gh < nsamp) {
                float2 p;
                p.x = (acc[mf][nf][2] - mH) * ss[nf][0] * rH + oo[nf][0];
                p.y = (acc[mf][nf][3] - mH) * ss[nf][1] * rH + oo[nf][1];
                *(float2*)(out + (size_t)gh * D + col) = p;
            }
        }
    }

    // reset winner for next invocation (last kernel in the pipeline)
    for (int gi = blockIdx.x * 256 + t; gi < ntotal; gi += gridDim.x * 256)
        g_winner[gi] = 0;
}

// -----------------------------------------------------------------------------
extern "C" void kernel_launch(void* const* d_in, const int* in_sizes, int n_in,
                              void* d_out, int out_size) {
    const float* x        = (const float*)d_in[0];
    const int*   adj_row  = (const int*)d_in[1];
    const int*   adj_col  = (const int*)d_in[2];
    const float* adj_val  = (const float*)d_in[3];
    const int*   nodes    = (const int*)d_in[4];
    const float* y_buf    = (const float*)d_in[5];
    const float* W        = (const float*)d_in[6];
    const float* b        = (const float*)d_in[7];
    const float* scale    = (const float*)d_in[8];
    const float* offset   = (const float*)d_in[9];

    int E      = in_sizes[1];
    int nsamp  = in_sizes[4];
    int nsrc   = in_sizes[0] / D;
    int ntotal = in_sizes[5] / D;

    float* out  = (float*)d_out;
    float* newY = out + (size_t)nsamp * D;

    int G = (nsamp + SCAN_EPB - 1) / SCAN_EPB;
    int spmmB  = (nsamp + 7) / 8;
    int decayB = (ntotal * D4 + 2047) / 2048;
    int scatB  = (E + 255) / 256;
    int convB  = (nsrc * D4 + 1023) / 1024;
    int wB     = (D * D + 255) / 256;

    // idempotent, capture-safe (attribute persists; no allocation involved)
    cudaFuncSetAttribute(k_gemm_mma, cudaFuncAttributeMaxDynamicSharedMemorySize,
                         SM_GEMM_TOTAL);

    k_hist<<<(E + 255) / 256, 256>>>(adj_row, E, nodes, nsamp);
    k_scan<<<G, SCAN_TPB>>>(nsamp, E);
    k_scatter_conv<<<scatB + convB + wB, 256>>>(adj_row, adj_col, adj_val, E, nsamp,
                                                x, W, nsrc, scatB, convB);
    k_spmm_decay<<<spmmB + decayB, 256>>>(nodes, (const float4*)y_buf, (float4*)newY,
                                          nsamp, ntotal, spmmB, decayB);
    k_gemm_mma<<<(nsamp + 63) / 64, 256, SM_GEMM_TOTAL>>>(b, scale, offset, out,
                                                          nsamp, ntotal);
}